// round 9
// baseline (speedup 1.0000x reference)
#include <cuda_runtime.h>
#include <cuda_fp16.h>
#include <math.h>
#include <stdint.h>

#define NN 50000
#define EE 1600000
#define ET (EE + NN)

// ------------------- scratch (device globals; no allocation allowed) -------
__device__ __half g_h1h[NN * 64];
__device__ __half g_hm[NN * 64];
__device__ __half g_h2h[NN * 128];
__device__ float g_asrc1[NN * 8];
__device__ float g_adst1[NN * 8];
__device__ float g_asrc2[NN];
__device__ float g_adst2[NN];
__device__ int   g_counts[NN];
__device__ int   g_cnt[NN];
__device__ int   g_rowoff[NN + 1];
__device__ int   g_csrsrc[ET];
__device__ int   g_blocksum[64];
// pre-transposed fp16 weights: Bt[n][k] = W[k][n]
__device__ __half g_B1[128 * 128];   // W_map
__device__ __half g_B2[64 * 128];    // W1
__device__ __half g_B3[128 * 64];    // W2

__device__ __forceinline__ float leaky(float x) { return x > 0.f ? x : 0.2f * x; }

__device__ __forceinline__ uint32_t smem_u32(const void* p) {
    uint32_t a;
    asm("{ .reg .u64 t; cvta.to.shared.u64 t, %1; cvt.u32.u64 %0, t; }" : "=r"(a) : "l"(p));
    return a;
}
__device__ __forceinline__ void ldsm4(uint32_t* r, uint32_t addr) {
    asm volatile("ldmatrix.sync.aligned.m8n8.x4.shared.b16 {%0,%1,%2,%3}, [%4];"
        : "=r"(r[0]), "=r"(r[1]), "=r"(r[2]), "=r"(r[3]) : "r"(addr));
}
__device__ __forceinline__ void mma16816(float* d, const uint32_t* a, const uint32_t* b) {
    asm volatile(
        "mma.sync.aligned.m16n8k16.row.col.f32.f16.f16.f32 "
        "{%0,%1,%2,%3}, {%4,%5,%6,%7}, {%8,%9}, {%0,%1,%2,%3};"
        : "+f"(d[0]), "+f"(d[1]), "+f"(d[2]), "+f"(d[3])
        : "r"(a[0]), "r"(a[1]), "r"(a[2]), "r"(a[3]), "r"(b[0]), "r"(b[1]));
}

// ------------------- weight prep: transpose to fp16 --------------------------
__global__ void prep_w_kernel(const float* __restrict__ Wm, const float* __restrict__ W1,
                              const float* __restrict__ W2)
{
    int i = blockIdx.x * 256 + threadIdx.x;
    if (i < 16384)      { int n = i >> 7, k = i & 127; g_B1[i] = __float2half(Wm[k * 128 + n]); }
    else if (i < 24576) { int j = i - 16384; int n = j >> 7, k = j & 127; g_B2[j] = __float2half(W1[k * 64 + n]); }
    else if (i < 32768) { int j = i - 24576; int n = j >> 6, k = j & 63;  g_B3[j] = __float2half(W2[k * 128 + n]); }
}

// ------------------- fused GEMM1+GEMM2 (+att1): x -> h1, asrc1, adst1 --------
__global__ void __launch_bounds__(256, 2) gemm12_kernel(
    const float* __restrict__ A32,
    const float* __restrict__ bias,
    const float* __restrict__ attS, const float* __restrict__ attD,
    __half* __restrict__ outh1,
    float* __restrict__ asrc, float* __restrict__ adst,
    int M)
{
    constexpr int LDA = 136;
    const int tid = threadIdx.x;
    const int warp = tid >> 5;
    const int lane = tid & 31;
    const int gid = lane >> 2;
    const int tig = lane & 3;
    const int row0 = blockIdx.x * 128;
    const int WM = (warp & 3) * 32;
    const int WN1 = (warp >> 2) * 64;
    const int WN2 = (warp >> 2) * 32;

    extern __shared__ char sm[];
    __half* sA  = (__half*)sm;
    __half* sB1 = sA + 128 * LDA;
    __half* sB2 = sB1 + 128 * LDA;
    float* sBias = (float*)(sB2 + 64 * LDA);
    float* sAS = sBias + 128;
    float* sAD = sAS + 64;

    for (int idx = tid; idx < 128 * 32; idx += 256) {
        int r = idx >> 5;
        int c = (idx & 31) * 4;
        int gr = row0 + r;
        float4 v = make_float4(0.f, 0.f, 0.f, 0.f);
        if (gr < M) v = *(const float4*)(A32 + (size_t)gr * 128 + c);
        __half2 p0 = __floats2half2_rn(v.x, v.y);
        __half2 p1 = __floats2half2_rn(v.z, v.w);
        *(uint2*)(sA + r * LDA + c) = make_uint2(*(uint32_t*)&p0, *(uint32_t*)&p1);
    }
    for (int idx = tid; idx < 128 * 16; idx += 256) {
        int n = idx >> 4;
        int c = (idx & 15) * 8;
        *(uint4*)(sB1 + n * LDA + c) = *(const uint4*)(g_B1 + n * 128 + c);
    }
    for (int idx = tid; idx < 64 * 16; idx += 256) {
        int n = idx >> 4;
        int c = (idx & 15) * 8;
        *(uint4*)(sB2 + n * LDA + c) = *(const uint4*)(g_B2 + n * 128 + c);
    }
    if (tid < 128) sBias[tid] = bias[tid];
    if (tid < 64) { sAS[tid] = attS[tid]; sAD[tid] = attD[tid]; }
    __syncthreads();

    const uint32_t uA = smem_u32(sA), uB1 = smem_u32(sB1), uB2 = smem_u32(sB2);
    const int a0off = (WM + (lane & 15)) * LDA + (lane >> 4) * 8;
    const int a1off = a0off + 16 * LDA;
    const int brow = lane & 7;
    const int bhalf = (lane >> 3) & 1;
    const int bsel = (lane >> 4) * 8 + brow;

    float acc[2][8][4];
#pragma unroll
    for (int m = 0; m < 2; m++)
#pragma unroll
        for (int t = 0; t < 8; t++)
#pragma unroll
            for (int j = 0; j < 4; j++) acc[m][t][j] = 0.f;

#pragma unroll
    for (int ks = 0; ks < 8; ks++) {
        uint32_t a0[4], a1[4];
        ldsm4(a0, uA + (uint32_t)(a0off + ks * 16) * 2);
        ldsm4(a1, uA + (uint32_t)(a1off + ks * 16) * 2);
#pragma unroll
        for (int p = 0; p < 4; p++) {
            int boff = (WN1 + p * 16 + bsel) * LDA + ks * 16 + bhalf * 8;
            uint32_t b[4];
            ldsm4(b, uB1 + (uint32_t)boff * 2);
            mma16816(acc[0][2 * p],     a0, b);
            mma16816(acc[0][2 * p + 1], a0, b + 2);
            mma16816(acc[1][2 * p],     a1, b);
            mma16816(acc[1][2 * p + 1], a1, b + 2);
        }
    }
    __syncthreads();

#pragma unroll
    for (int m = 0; m < 2; m++) {
        int lr0 = WM + m * 16 + gid;
        int lr1 = lr0 + 8;
#pragma unroll
        for (int t = 0; t < 8; t++) {
            int c = WN1 + t * 8 + tig * 2;
            __half2 p0 = __floats2half2_rn(acc[m][t][0] + sBias[c], acc[m][t][1] + sBias[c + 1]);
            __half2 p1 = __floats2half2_rn(acc[m][t][2] + sBias[c], acc[m][t][3] + sBias[c + 1]);
            *(uint32_t*)(sA + lr0 * LDA + c) = *(uint32_t*)&p0;
            *(uint32_t*)(sA + lr1 * LDA + c) = *(uint32_t*)&p1;
        }
    }
    __syncthreads();

    float acc2[2][4][4];
#pragma unroll
    for (int m = 0; m < 2; m++)
#pragma unroll
        for (int t = 0; t < 4; t++)
#pragma unroll
            for (int j = 0; j < 4; j++) acc2[m][t][j] = 0.f;

#pragma unroll
    for (int ks = 0; ks < 8; ks++) {
        uint32_t a0[4], a1[4];
        ldsm4(a0, uA + (uint32_t)(a0off + ks * 16) * 2);
        ldsm4(a1, uA + (uint32_t)(a1off + ks * 16) * 2);
#pragma unroll
        for (int p = 0; p < 2; p++) {
            int boff = (WN2 + p * 16 + bsel) * LDA + ks * 16 + bhalf * 8;
            uint32_t b[4];
            ldsm4(b, uB2 + (uint32_t)boff * 2);
            mma16816(acc2[0][2 * p],     a0, b);
            mma16816(acc2[0][2 * p + 1], a0, b + 2);
            mma16816(acc2[1][2 * p],     a1, b);
            mma16816(acc2[1][2 * p + 1], a1, b + 2);
        }
    }

#pragma unroll
    for (int m = 0; m < 2; m++) {
        int r0 = row0 + WM + m * 16 + gid;
        int r1 = r0 + 8;
#pragma unroll
        for (int t = 0; t < 4; t++) {
            int c = WN2 + t * 8 + tig * 2;
            int head = (WN2 >> 3) + t;
            float sl  = acc2[m][t][0] * sAS[c] + acc2[m][t][1] * sAS[c + 1];
            float shh = acc2[m][t][2] * sAS[c] + acc2[m][t][3] * sAS[c + 1];
            float dl  = acc2[m][t][0] * sAD[c] + acc2[m][t][1] * sAD[c + 1];
            float dhh = acc2[m][t][2] * sAD[c] + acc2[m][t][3] * sAD[c + 1];
#pragma unroll
            for (int o = 1; o < 4; o <<= 1) {
                sl  += __shfl_xor_sync(0xFFFFFFFFu, sl, o);
                shh += __shfl_xor_sync(0xFFFFFFFFu, shh, o);
                dl  += __shfl_xor_sync(0xFFFFFFFFu, dl, o);
                dhh += __shfl_xor_sync(0xFFFFFFFFu, dhh, o);
            }
            if (tig == 0) {
                if (r0 < M) { asrc[(size_t)r0 * 8 + head] = sl;  adst[(size_t)r0 * 8 + head] = dl; }
                if (r1 < M) { asrc[(size_t)r1 * 8 + head] = shh; adst[(size_t)r1 * 8 + head] = dhh; }
            }
            __half2 p0 = __floats2half2_rn(acc2[m][t][0], acc2[m][t][1]);
            __half2 p1 = __floats2half2_rn(acc2[m][t][2], acc2[m][t][3]);
            if (r0 < M) *(uint32_t*)(outh1 + (size_t)r0 * 64 + c) = *(uint32_t*)&p0;
            if (r1 < M) *(uint32_t*)(outh1 + (size_t)r1 * 64 + c) = *(uint32_t*)&p1;
        }
    }
}
#define SMEM_G12 ((128 + 128 + 64) * 136 * 2 + 128 * 4 + 64 * 8 + 256)

// ------------------- GEMM3 (+att2): hm -> h2, asrc2, adst2 -------------------
__global__ void __launch_bounds__(256) gemm3_kernel(
    const __half* __restrict__ Ag,
    const float* __restrict__ attS, const float* __restrict__ attD,
    __half* __restrict__ outhalf,
    float* __restrict__ asrc, float* __restrict__ adst,
    int M)
{
    constexpr int K = 64, NC = 128, LDA = 72;
    const int tid = threadIdx.x;
    const int warp = tid >> 5;
    const int lane = tid & 31;
    const int gid = lane >> 2;
    const int tig = lane & 3;
    const int row0 = blockIdx.x * 128;
    const int WM = (warp & 3) * 32;
    const int WN = (warp >> 2) * 64;

    extern __shared__ char sm[];
    __half* sA = (__half*)sm;
    __half* sB = sA + 128 * LDA;
    float* sF  = (float*)(sB + NC * LDA);
    float* sF2 = sF + NC;
    float* sRed = sF2 + NC;

    for (int idx = tid; idx < 128 * (K / 8); idx += 256) {
        int r = idx / (K / 8);
        int c = (idx % (K / 8)) * 8;
        int gr = row0 + r;
        uint4 v = make_uint4(0, 0, 0, 0);
        if (gr < M) v = *(const uint4*)(Ag + (size_t)gr * K + c);
        *(uint4*)(sA + r * LDA + c) = v;
    }
    for (int idx = tid; idx < NC * (K / 8); idx += 256) {
        int n = idx / (K / 8);
        int c = (idx % (K / 8)) * 8;
        *(uint4*)(sB + n * LDA + c) = *(const uint4*)(g_B3 + n * K + c);
    }
    if (tid < NC) { sF[tid] = attS[tid]; sF2[tid] = attD[tid]; }
    __syncthreads();

    float acc[2][8][4];
#pragma unroll
    for (int m = 0; m < 2; m++)
#pragma unroll
        for (int t = 0; t < 8; t++)
#pragma unroll
            for (int j = 0; j < 4; j++) acc[m][t][j] = 0.f;

    const uint32_t uA = smem_u32(sA), uB = smem_u32(sB);
    const int a0off = (WM + (lane & 15)) * LDA + (lane >> 4) * 8;
    const int a1off = a0off + 16 * LDA;
    const int brow = lane & 7;
    const int bhalf = (lane >> 3) & 1;
    const int bsel = (lane >> 4) * 8 + brow;

#pragma unroll
    for (int ks = 0; ks < K / 16; ks++) {
        uint32_t a0[4], a1[4];
        ldsm4(a0, uA + (uint32_t)(a0off + ks * 16) * 2);
        ldsm4(a1, uA + (uint32_t)(a1off + ks * 16) * 2);
#pragma unroll
        for (int p = 0; p < 4; p++) {
            int boff = (WN + p * 16 + bsel) * LDA + ks * 16 + bhalf * 8;
            uint32_t b[4];
            ldsm4(b, uB + (uint32_t)boff * 2);
            mma16816(acc[0][2 * p],     a0, b);
            mma16816(acc[0][2 * p + 1], a0, b + 2);
            mma16816(acc[1][2 * p],     a1, b);
            mma16816(acc[1][2 * p + 1], a1, b + 2);
        }
    }

    float s[2] = {0.f, 0.f}, d[2] = {0.f, 0.f};
    float sh[2] = {0.f, 0.f}, dh[2] = {0.f, 0.f};
#pragma unroll
    for (int m = 0; m < 2; m++)
#pragma unroll
        for (int t = 0; t < 8; t++) {
            int c = WN + t * 8 + tig * 2;
            s[m]  += acc[m][t][0] * sF[c]  + acc[m][t][1] * sF[c + 1];
            sh[m] += acc[m][t][2] * sF[c]  + acc[m][t][3] * sF[c + 1];
            d[m]  += acc[m][t][0] * sF2[c] + acc[m][t][1] * sF2[c + 1];
            dh[m] += acc[m][t][2] * sF2[c] + acc[m][t][3] * sF2[c + 1];
        }
#pragma unroll
    for (int m = 0; m < 2; m++)
#pragma unroll
        for (int o = 1; o < 4; o <<= 1) {
            s[m]  += __shfl_xor_sync(0xFFFFFFFFu, s[m], o);
            sh[m] += __shfl_xor_sync(0xFFFFFFFFu, sh[m], o);
            d[m]  += __shfl_xor_sync(0xFFFFFFFFu, d[m], o);
            dh[m] += __shfl_xor_sync(0xFFFFFFFFu, dh[m], o);
        }
    if (warp >= 4 && tig == 0) {
#pragma unroll
        for (int m = 0; m < 2; m++) {
            int lr = WM + m * 16 + gid;
            sRed[lr * 2] = s[m];            sRed[lr * 2 + 1] = d[m];
            sRed[(lr + 8) * 2] = sh[m];     sRed[(lr + 8) * 2 + 1] = dh[m];
        }
    }
    __syncthreads();
    if (warp < 4 && tig == 0) {
#pragma unroll
        for (int m = 0; m < 2; m++) {
            int lr = WM + m * 16 + gid;
            int r0 = row0 + lr, r1 = r0 + 8;
            if (r0 < M) { asrc[r0] = s[m]  + sRed[lr * 2];       adst[r0] = d[m]  + sRed[lr * 2 + 1]; }
            if (r1 < M) { asrc[r1] = sh[m] + sRed[(lr + 8) * 2]; adst[r1] = dh[m] + sRed[(lr + 8) * 2 + 1]; }
        }
    }

#pragma unroll
    for (int m = 0; m < 2; m++) {
        int r0 = row0 + WM + m * 16 + gid;
        int r1 = r0 + 8;
#pragma unroll
        for (int t = 0; t < 8; t++) {
            int c = WN + t * 8 + tig * 2;
            __half2 p0 = __floats2half2_rn(acc[m][t][0], acc[m][t][1]);
            __half2 p1 = __floats2half2_rn(acc[m][t][2], acc[m][t][3]);
            if (r0 < M) *(uint32_t*)(outhalf + (size_t)r0 * NC + c) = *(uint32_t*)&p0;
            if (r1 < M) *(uint32_t*)(outhalf + (size_t)r1 * NC + c) = *(uint32_t*)&p1;
        }
    }
}
#define SMEM_G3 ((128 + 128) * 72 * 2 + 128 * 8 + 128 * 8 + 256)

// ------------------- static init ---------------------------------------------
struct HxInit {
    cudaStream_t s2;
    cudaEvent_t evF, evJ;
    HxInit() {
        cudaStreamCreateWithFlags(&s2, cudaStreamNonBlocking);
        cudaEventCreateWithFlags(&evF, cudaEventDisableTiming);
        cudaEventCreateWithFlags(&evJ, cudaEventDisableTiming);
        cudaFuncSetAttribute(gemm12_kernel, cudaFuncAttributeMaxDynamicSharedMemorySize, SMEM_G12);
        cudaFuncSetAttribute(gemm3_kernel,  cudaFuncAttributeMaxDynamicSharedMemorySize, SMEM_G3);
    }
};
static HxInit g_hx;

// ------------------- CSR build ----------------------------------------------
__global__ void init_kernel()
{
    int i = blockIdx.x * 256 + threadIdx.x;
    if (i < NN) g_counts[i] = 1;   // self loop
}

// vectorized: 4 edges per thread
__global__ void count_kernel(const int* __restrict__ dst)
{
    int t = blockIdx.x * 256 + threadIdx.x;
    if (t * 4 >= EE) return;
    int4 d4 = *(const int4*)(dst + t * 4);
    atomicAdd(&g_counts[d4.x], 1);
    atomicAdd(&g_counts[d4.y], 1);
    atomicAdd(&g_counts[d4.z], 1);
    atomicAdd(&g_counts[d4.w], 1);
}

__global__ void __launch_bounds__(1024) scan1_kernel()
{
    __shared__ int wsum[32];
    int tid = threadIdx.x, lane = tid & 31, wid = tid >> 5;
    int idx = blockIdx.x * 1024 + tid;
    int v = (idx < NN) ? g_counts[idx] : 0;
    int x = v;
#pragma unroll
    for (int off = 1; off < 32; off <<= 1) {
        int y = __shfl_up_sync(0xFFFFFFFFu, x, off);
        if (lane >= off) x += y;
    }
    if (lane == 31) wsum[wid] = x;
    __syncthreads();
    if (wid == 0) {
        int wv = wsum[lane];
#pragma unroll
        for (int off = 1; off < 32; off <<= 1) {
            int y = __shfl_up_sync(0xFFFFFFFFu, wv, off);
            if (lane >= off) wv += y;
        }
        wsum[lane] = wv;
    }
    __syncthreads();
    int pre = (wid > 0) ? wsum[wid - 1] : 0;
    if (idx < NN) g_rowoff[idx] = x + pre - v;
    if (tid == 1023) g_blocksum[blockIdx.x] = x + pre;
}

__global__ void __launch_bounds__(64) scan2_kernel(int nblocks)
{
    __shared__ int s0tot;
    int tid = threadIdx.x, lane = tid & 31, wid = tid >> 5;
    int v = (tid < nblocks) ? g_blocksum[tid] : 0;
    int x = v;
#pragma unroll
    for (int off = 1; off < 32; off <<= 1) {
        int y = __shfl_up_sync(0xFFFFFFFFu, x, off);
        if (lane >= off) x += y;
    }
    if (wid == 0 && lane == 31) s0tot = x;
    __syncthreads();
    int pre = (wid == 1) ? s0tot : 0;
    int excl = x - v + pre;
    if (tid < nblocks) g_blocksum[tid] = excl;
    if (tid == nblocks - 1) g_rowoff[NN] = excl + v;
}

// adds block offsets, seeds insert pointers, writes self-loop entries
__global__ void __launch_bounds__(1024) scan3_kernel()
{
    int idx = blockIdx.x * 1024 + threadIdx.x;
    if (idx < NN) {
        int off = g_rowoff[idx] + g_blocksum[blockIdx.x];
        g_rowoff[idx] = off;
        g_cnt[idx] = off + 1;       // insert pointer (slot 0 = self loop)
        g_csrsrc[off] = idx;        // self loop
    }
}

// vectorized: 4 edges per thread; pos via seeded atomic pointer only
__global__ void scatter_kernel(const int* __restrict__ src, const int* __restrict__ dst)
{
    int t = blockIdx.x * 256 + threadIdx.x;
    if (t * 4 >= EE) return;
    int4 s4 = *(const int4*)(src + t * 4);
    int4 d4 = *(const int4*)(dst + t * 4);
    g_csrsrc[atomicAdd(&g_cnt[d4.x], 1)] = s4.x;
    g_csrsrc[atomicAdd(&g_cnt[d4.y], 1)] = s4.y;
    g_csrsrc[atomicAdd(&g_cnt[d4.z], 1)] = s4.z;
    g_csrsrc[atomicAdd(&g_cnt[d4.w], 1)] = s4.w;
}

// ------------------- GAT conv1 aggregation (single pass, 8-way unroll) -------
__global__ void __launch_bounds__(256) agg1_kernel(const float* __restrict__ b1)
{
    int w = (blockIdx.x * blockDim.x + threadIdx.x) >> 5;
    int lane = threadIdx.x & 31;
    if (w >= NN) return;
    int head = lane >> 2;
    int c0 = lane * 2;
    int beg = g_rowoff[w], end = g_rowoff[w + 1];

    float adh = g_adst1[w * 8 + head];

    float a0 = 0.f, a1 = 0.f, sA = 0.f;
    float p0b = 0.f, p1b = 0.f, sB = 0.f;
    float q0 = 0.f, q1 = 0.f, sC = 0.f;
    float r0 = 0.f, r1 = 0.f, sD = 0.f;
    int j = beg;
    for (; j + 8 <= end; j += 8) {
        int s0 = g_csrsrc[j],     s1 = g_csrsrc[j + 1], s2 = g_csrsrc[j + 2], s3 = g_csrsrc[j + 3];
        int s4 = g_csrsrc[j + 4], s5 = g_csrsrc[j + 5], s6 = g_csrsrc[j + 6], s7 = g_csrsrc[j + 7];
        float e0 = __expf(leaky(g_asrc1[s0 * 8 + head] + adh));
        float e1 = __expf(leaky(g_asrc1[s1 * 8 + head] + adh));
        float e2 = __expf(leaky(g_asrc1[s2 * 8 + head] + adh));
        float e3 = __expf(leaky(g_asrc1[s3 * 8 + head] + adh));
        float e4 = __expf(leaky(g_asrc1[s4 * 8 + head] + adh));
        float e5 = __expf(leaky(g_asrc1[s5 * 8 + head] + adh));
        float e6 = __expf(leaky(g_asrc1[s6 * 8 + head] + adh));
        float e7 = __expf(leaky(g_asrc1[s7 * 8 + head] + adh));
        float2 h0 = __half22float2(*(const __half2*)(g_h1h + s0 * 64 + c0));
        float2 h1v = __half22float2(*(const __half2*)(g_h1h + s1 * 64 + c0));
        float2 h2v = __half22float2(*(const __half2*)(g_h1h + s2 * 64 + c0));
        float2 h3v = __half22float2(*(const __half2*)(g_h1h + s3 * 64 + c0));
        float2 h4v = __half22float2(*(const __half2*)(g_h1h + s4 * 64 + c0));
        float2 h5v = __half22float2(*(const __half2*)(g_h1h + s5 * 64 + c0));
        float2 h6v = __half22float2(*(const __half2*)(g_h1h + s6 * 64 + c0));
        float2 h7v = __half22float2(*(const __half2*)(g_h1h + s7 * 64 + c0));
        a0 = fmaf(e0, h0.x, a0);  a1 = fmaf(e0, h0.y, a1);  sA += e0;
        p0b = fmaf(e1, h1v.x, p0b); p1b = fmaf(e1, h1v.y, p1b); sB += e1;
        q0 = fmaf(e2, h2v.x, q0); q1 = fmaf(e2, h2v.y, q1); sC += e2;
        r0 = fmaf(e3, h3v.x, r0); r1 = fmaf(e3, h3v.y, r1); sD += e3;
        a0 = fmaf(e4, h4v.x, a0);  a1 = fmaf(e4, h4v.y, a1);  sA += e4;
        p0b = fmaf(e5, h5v.x, p0b); p1b = fmaf(e5, h5v.y, p1b); sB += e5;
        q0 = fmaf(e6, h6v.x, q0); q1 = fmaf(e6, h6v.y, q1); sC += e6;
        r0 = fmaf(e7, h7v.x, r0); r1 = fmaf(e7, h7v.y, r1); sD += e7;
    }
    for (; j + 4 <= end; j += 4) {
        int s0 = g_csrsrc[j], s1 = g_csrsrc[j + 1], s2 = g_csrsrc[j + 2], s3 = g_csrsrc[j + 3];
        float e0 = __expf(leaky(g_asrc1[s0 * 8 + head] + adh));
        float e1 = __expf(leaky(g_asrc1[s1 * 8 + head] + adh));
        float e2 = __expf(leaky(g_asrc1[s2 * 8 + head] + adh));
        float e3 = __expf(leaky(g_asrc1[s3 * 8 + head] + adh));
        float2 h0 = __half22float2(*(const __half2*)(g_h1h + s0 * 64 + c0));
        float2 h1v = __half22float2(*(const __half2*)(g_h1h + s1 * 64 + c0));
        float2 h2v = __half22float2(*(const __half2*)(g_h1h + s2 * 64 + c0));
        float2 h3v = __half22float2(*(const __half2*)(g_h1h + s3 * 64 + c0));
        a0 = fmaf(e0, h0.x, a0);  a1 = fmaf(e0, h0.y, a1);  sA += e0;
        p0b = fmaf(e1, h1v.x, p0b); p1b = fmaf(e1, h1v.y, p1b); sB += e1;
        q0 = fmaf(e2, h2v.x, q0); q1 = fmaf(e2, h2v.y, q1); sC += e2;
        r0 = fmaf(e3, h3v.x, r0); r1 = fmaf(e3, h3v.y, r1); sD += e3;
    }
    for (; j < end; j++) {
        int s = g_csrsrc[j];
        float e = __expf(leaky(g_asrc1[s * 8 + head] + adh));
        float2 hv = __half22float2(*(const __half2*)(g_h1h + s * 64 + c0));
        a0 = fmaf(e, hv.x, a0); a1 = fmaf(e, hv.y, a1); sA += e;
    }
    a0 += p0b + q0 + r0;
    a1 += p1b + q1 + r1;
    sA += sB + sC + sD;
    float inv = 1.f / sA;
    float o0 = a0 * inv + b1[c0];
    float o1 = a1 * inv + b1[c0 + 1];
    o0 = o0 > 0.f ? o0 : expm1f(o0);
    o1 = o1 > 0.f ? o1 : expm1f(o1);
    __half2 p = __floats2half2_rn(o0, o1);
    *(uint32_t*)(g_hm + w * 64 + c0) = *(uint32_t*)&p;
}

// ------------------- GAT conv2 aggregation (single pass, no max) -------------
__device__ __forceinline__ void h4acc(uint2 u, float e, float4& a)
{
    float2 f0 = __half22float2(*(__half2*)&u.x);
    float2 f1 = __half22float2(*(__half2*)&u.y);
    a.x = fmaf(e, f0.x, a.x); a.y = fmaf(e, f0.y, a.y);
    a.z = fmaf(e, f1.x, a.z); a.w = fmaf(e, f1.y, a.w);
}

__global__ void __launch_bounds__(256) agg2_kernel(
    const float* __restrict__ b2, float* __restrict__ out)
{
    int w = (blockIdx.x * blockDim.x + threadIdx.x) >> 5;
    int lane = threadIdx.x & 31;
    if (w >= NN) return;
    int c0 = lane * 4;
    int beg = g_rowoff[w], end = g_rowoff[w + 1];
    float adh = g_adst2[w];

    float4 aA = make_float4(0.f, 0.f, 0.f, 0.f);
    float4 aB = make_float4(0.f, 0.f, 0.f, 0.f);
    float4 aC = make_float4(0.f, 0.f, 0.f, 0.f);
    float4 aD = make_float4(0.f, 0.f, 0.f, 0.f);
    float sA = 0.f, sB = 0.f, sC = 0.f, sD = 0.f;
    int j = beg;
    for (; j + 8 <= end; j += 8) {
        int s0 = g_csrsrc[j],     s1 = g_csrsrc[j + 1], s2 = g_csrsrc[j + 2], s3 = g_csrsrc[j + 3];
        int s4 = g_csrsrc[j + 4], s5 = g_csrsrc[j + 5], s6 = g_csrsrc[j + 6], s7 = g_csrsrc[j + 7];
        float e0 = __expf(leaky(g_asrc2[s0] + adh));
        float e1 = __expf(leaky(g_asrc2[s1] + adh));
        float e2 = __expf(leaky(g_asrc2[s2] + adh));
        float e3 = __expf(leaky(g_asrc2[s3] + adh));
        float e4 = __expf(leaky(g_asrc2[s4] + adh));
        float e5 = __expf(leaky(g_asrc2[s5] + adh));
        float e6 = __expf(leaky(g_asrc2[s6] + adh));
        float e7 = __expf(leaky(g_asrc2[s7] + adh));
        uint2 u0 = *(const uint2*)(g_h2h + s0 * 128 + c0);
        uint2 u1 = *(const uint2*)(g_h2h + s1 * 128 + c0);
        uint2 u2 = *(const uint2*)(g_h2h + s2 * 128 + c0);
        uint2 u3 = *(const uint2*)(g_h2h + s3 * 128 + c0);
        uint2 u4 = *(const uint2*)(g_h2h + s4 * 128 + c0);
        uint2 u5 = *(const uint2*)(g_h2h + s5 * 128 + c0);
        uint2 u6 = *(const uint2*)(g_h2h + s6 * 128 + c0);
        uint2 u7 = *(const uint2*)(g_h2h + s7 * 128 + c0);
        h4acc(u0, e0, aA); sA += e0;
        h4acc(u1, e1, aB); sB += e1;
        h4acc(u2, e2, aC); sC += e2;
        h4acc(u3, e3, aD); sD += e3;
        h4acc(u4, e4, aA); sA += e4;
        h4acc(u5, e5, aB); sB += e5;
        h4acc(u6, e6, aC); sC += e6;
        h4acc(u7, e7, aD); sD += e7;
    }
    for (; j + 4 <= end; j += 4) {
        int s0 = g_csrsrc[j], s1 = g_csrsrc[j + 1], s2 = g_csrsrc[j + 2], s3 = g_csrsrc[j + 3];
        float e0 = __expf(leaky(g_asrc2[s0] + adh));
        float e1 = __expf(leaky(g_asrc2[s1] + adh));
        float e2 = __expf(leaky(g_asrc2[s2] + adh));
        float e3 = __expf(leaky(g_asrc2[s3] + adh));
        uint2 u0 = *(const uint2*)(g_h2h + s0 * 128 + c0);
        uint2 u1 = *(const uint2*)(g_h2h + s1 * 128 + c0);
        uint2 u2 = *(const uint2*)(g_h2h + s2 * 128 + c0);
        uint2 u3 = *(const uint2*)(g_h2h + s3 * 128 + c0);
        h4acc(u0, e0, aA); sA += e0;
        h4acc(u1, e1, aB); sB += e1;
        h4acc(u2, e2, aC); sC += e2;
        h4acc(u3, e3, aD); sD += e3;
    }
    for (; j < end; j++) {
        int s = g_csrsrc[j];
        float e = __expf(leaky(g_asrc2[s] + adh));
        uint2 u = *(const uint2*)(g_h2h + s * 128 + c0);
        h4acc(u, e, aA); sA += e;
    }
    aA.x += aB.x + aC.x + aD.x;
    aA.y += aB.y + aC.y + aD.y;
    aA.z += aB.z + aC.z + aD.z;
    aA.w += aB.w + aC.w + aD.w;
    sA += sB + sC + sD;
    float inv = 1.f / sA;
    float4 bb = *(const float4*)(b2 + c0);
    float4 o;
    o.x = aA.x * inv + bb.x;
    o.y = aA.y * inv + bb.y;
    o.z = aA.z * inv + bb.z;
    o.w = aA.w * inv + bb.w;
    *(float4*)(out + w * 128 + c0) = o;
}

// ------------------- launch --------------------------------------------------
extern "C" void kernel_launch(void* const* d_in, const int* in_sizes, int n_in,
                              void* d_out, int out_size)
{
    (void)in_sizes; (void)n_in; (void)out_size;
    const float* x        = (const float*)d_in[0];
    const int*   ei       = (const int*)d_in[1];
    const float* W_map    = (const float*)d_in[2];
    const float* b_map    = (const float*)d_in[3];
    const float* W1       = (const float*)d_in[4];
    const float* att_src1 = (const float*)d_in[5];
    const float* att_dst1 = (const float*)d_in[6];
    const float* b1       = (const float*)d_in[7];
    const float* W2       = (const float*)d_in[8];
    const float* att_src2 = (const float*)d_in[9];
    const float* att_dst2 = (const float*)d_in[10];
    const float* b2       = (const float*)d_in[11];
    float* out = (float*)d_out;
    const int* src = ei;
    const int* dst = ei + EE;

    __half *p_h1h, *p_hm, *p_h2h;
    float *p_as1, *p_ad1, *p_as2, *p_ad2;
    cudaGetSymbolAddress((void**)&p_h1h, g_h1h);
    cudaGetSymbolAddress((void**)&p_hm, g_hm);
    cudaGetSymbolAddress((void**)&p_h2h, g_h2h);
    cudaGetSymbolAddress((void**)&p_as1, g_asrc1);
    cudaGetSymbolAddress((void**)&p_ad1, g_adst1);
    cudaGetSymbolAddress((void**)&p_as2, g_asrc2);
    cudaGetSymbolAddress((void**)&p_ad2, g_adst2);

    const int GEMM_BLOCKS = (NN + 127) / 128;
    const int N_BLOCKS    = (NN + 255) / 256;
    const int E4_BLOCKS   = (EE / 4 + 255) / 256;   // 1563
    const int WARP_BLOCKS = NN / 8;
    const int SCAN_BLOCKS = (NN + 1023) / 1024;

    cudaStream_t s2 = g_hx.s2;

    prep_w_kernel<<<128, 256>>>(W_map, W1, W2);

    cudaEventRecord(g_hx.evF, 0);
    cudaStreamWaitEvent(s2, g_hx.evF, 0);
    init_kernel<<<N_BLOCKS, 256, 0, s2>>>();
    count_kernel<<<E4_BLOCKS, 256, 0, s2>>>(dst);

    gemm12_kernel<<<GEMM_BLOCKS, 256, SMEM_G12>>>(
        x, b_map, att_src1, att_dst1, p_h1h, p_as1, p_ad1, NN);

    scan1_kernel<<<SCAN_BLOCKS, 1024, 0, s2>>>();
    scan2_kernel<<<1, 64, 0, s2>>>(SCAN_BLOCKS);
    scan3_kernel<<<SCAN_BLOCKS, 1024, 0, s2>>>();
    scatter_kernel<<<E4_BLOCKS, 256, 0, s2>>>(src, dst);
    cudaEventRecord(g_hx.evJ, s2);

    cudaStreamWaitEvent(0, g_hx.evJ, 0);

    agg1_kernel<<<WARP_BLOCKS, 256>>>(b1);
    gemm3_kernel<<<GEMM_BLOCKS, 256, SMEM_G3>>>(
        p_hm, att_src2, att_dst2, p_h2h, p_as2, p_ad2, NN);
    agg2_kernel<<<WARP_BLOCKS, 256>>>(b2, out);
}

// round 10
// speedup vs baseline: 1.0510x; 1.0510x over previous
#include <cuda_runtime.h>
#include <cuda_fp16.h>
#include <math.h>
#include <stdint.h>

#define NN 50000
#define EE 1600000
#define ET (EE + NN)

// ------------------- scratch (device globals; no allocation allowed) -------
__device__ __half g_h1h[NN * 64];
__device__ __half g_hm[NN * 64];     // conv1 output (post-ELU)
__device__ __half g_aggh[NN * 64];   // conv2 aggregated hm (pre-W2)
__device__ float g_asrc1[NN * 8];
__device__ float g_adst1[NN * 8];
__device__ float g_asrc2[NN];
__device__ float g_adst2[NN];
__device__ int   g_counts[NN];
__device__ int   g_cnt[NN];
__device__ int   g_rowoff[NN + 1];
__device__ int   g_csrsrc[ET];
__device__ int   g_blocksum[64];
__device__ float g_wsd[128];         // [0:64) = W2@att_src2, [64:128) = W2@att_dst2
// pre-transposed fp16 weights: Bt[n][k] = W[k][n]
__device__ __half g_B1[128 * 128];   // W_map
__device__ __half g_B2[64 * 128];    // W1
__device__ __half g_B3[128 * 64];    // W2

__device__ __forceinline__ float leaky(float x) { return x > 0.f ? x : 0.2f * x; }

__device__ __forceinline__ uint32_t smem_u32(const void* p) {
    uint32_t a;
    asm("{ .reg .u64 t; cvta.to.shared.u64 t, %1; cvt.u32.u64 %0, t; }" : "=r"(a) : "l"(p));
    return a;
}
__device__ __forceinline__ void ldsm4(uint32_t* r, uint32_t addr) {
    asm volatile("ldmatrix.sync.aligned.m8n8.x4.shared.b16 {%0,%1,%2,%3}, [%4];"
        : "=r"(r[0]), "=r"(r[1]), "=r"(r[2]), "=r"(r[3]) : "r"(addr));
}
__device__ __forceinline__ void mma16816(float* d, const uint32_t* a, const uint32_t* b) {
    asm volatile(
        "mma.sync.aligned.m16n8k16.row.col.f32.f16.f16.f32 "
        "{%0,%1,%2,%3}, {%4,%5,%6,%7}, {%8,%9}, {%0,%1,%2,%3};"
        : "+f"(d[0]), "+f"(d[1]), "+f"(d[2]), "+f"(d[3])
        : "r"(a[0]), "r"(a[1]), "r"(a[2]), "r"(a[3]), "r"(b[0]), "r"(b[1]));
}

// ------------------- weight prep: transpose to fp16 + W2-folded att vectors --
__global__ void prep_w_kernel(const float* __restrict__ Wm, const float* __restrict__ W1,
                              const float* __restrict__ W2,
                              const float* __restrict__ attS2, const float* __restrict__ attD2)
{
    int i = blockIdx.x * 256 + threadIdx.x;
    if (i < 16384)      { int n = i >> 7, k = i & 127; g_B1[i] = __float2half(Wm[k * 128 + n]); }
    else if (i < 24576) { int j = i - 16384; int n = j >> 7, k = j & 127; g_B2[j] = __float2half(W1[k * 64 + n]); }
    else if (i < 32768) { int j = i - 24576; int n = j >> 6, k = j & 63;  g_B3[j] = __float2half(W2[k * 128 + n]); }
    else if (i < 32832) {
        int k = i - 32768;   // 0..63
        float s = 0.f, d = 0.f;
        const float* row = W2 + k * 128;
#pragma unroll 4
        for (int n = 0; n < 128; n++) {
            s = fmaf(row[n], attS2[n], s);
            d = fmaf(row[n], attD2[n], d);
        }
        g_wsd[k] = s;
        g_wsd[64 + k] = d;
    }
}

// ------------------- fused GEMM1+GEMM2 (+att1): x -> h1, asrc1, adst1 --------
__global__ void __launch_bounds__(256, 2) gemm12_kernel(
    const float* __restrict__ A32,
    const float* __restrict__ bias,
    const float* __restrict__ attS, const float* __restrict__ attD,
    __half* __restrict__ outh1,
    float* __restrict__ asrc, float* __restrict__ adst,
    int M)
{
    constexpr int LDA = 136;
    const int tid = threadIdx.x;
    const int warp = tid >> 5;
    const int lane = tid & 31;
    const int gid = lane >> 2;
    const int tig = lane & 3;
    const int row0 = blockIdx.x * 128;
    const int WM = (warp & 3) * 32;
    const int WN1 = (warp >> 2) * 64;
    const int WN2 = (warp >> 2) * 32;

    extern __shared__ char sm[];
    __half* sA  = (__half*)sm;
    __half* sB1 = sA + 128 * LDA;
    __half* sB2 = sB1 + 128 * LDA;
    float* sBias = (float*)(sB2 + 64 * LDA);
    float* sAS = sBias + 128;
    float* sAD = sAS + 64;

    for (int idx = tid; idx < 128 * 32; idx += 256) {
        int r = idx >> 5;
        int c = (idx & 31) * 4;
        int gr = row0 + r;
        float4 v = make_float4(0.f, 0.f, 0.f, 0.f);
        if (gr < M) v = *(const float4*)(A32 + (size_t)gr * 128 + c);
        __half2 p0 = __floats2half2_rn(v.x, v.y);
        __half2 p1 = __floats2half2_rn(v.z, v.w);
        *(uint2*)(sA + r * LDA + c) = make_uint2(*(uint32_t*)&p0, *(uint32_t*)&p1);
    }
    for (int idx = tid; idx < 128 * 16; idx += 256) {
        int n = idx >> 4;
        int c = (idx & 15) * 8;
        *(uint4*)(sB1 + n * LDA + c) = *(const uint4*)(g_B1 + n * 128 + c);
    }
    for (int idx = tid; idx < 64 * 16; idx += 256) {
        int n = idx >> 4;
        int c = (idx & 15) * 8;
        *(uint4*)(sB2 + n * LDA + c) = *(const uint4*)(g_B2 + n * 128 + c);
    }
    if (tid < 128) sBias[tid] = bias[tid];
    if (tid < 64) { sAS[tid] = attS[tid]; sAD[tid] = attD[tid]; }
    __syncthreads();

    const uint32_t uA = smem_u32(sA), uB1 = smem_u32(sB1), uB2 = smem_u32(sB2);
    const int a0off = (WM + (lane & 15)) * LDA + (lane >> 4) * 8;
    const int a1off = a0off + 16 * LDA;
    const int brow = lane & 7;
    const int bhalf = (lane >> 3) & 1;
    const int bsel = (lane >> 4) * 8 + brow;

    float acc[2][8][4];
#pragma unroll
    for (int m = 0; m < 2; m++)
#pragma unroll
        for (int t = 0; t < 8; t++)
#pragma unroll
            for (int j = 0; j < 4; j++) acc[m][t][j] = 0.f;

#pragma unroll
    for (int ks = 0; ks < 8; ks++) {
        uint32_t a0[4], a1[4];
        ldsm4(a0, uA + (uint32_t)(a0off + ks * 16) * 2);
        ldsm4(a1, uA + (uint32_t)(a1off + ks * 16) * 2);
#pragma unroll
        for (int p = 0; p < 4; p++) {
            int boff = (WN1 + p * 16 + bsel) * LDA + ks * 16 + bhalf * 8;
            uint32_t b[4];
            ldsm4(b, uB1 + (uint32_t)boff * 2);
            mma16816(acc[0][2 * p],     a0, b);
            mma16816(acc[0][2 * p + 1], a0, b + 2);
            mma16816(acc[1][2 * p],     a1, b);
            mma16816(acc[1][2 * p + 1], a1, b + 2);
        }
    }
    __syncthreads();

#pragma unroll
    for (int m = 0; m < 2; m++) {
        int lr0 = WM + m * 16 + gid;
        int lr1 = lr0 + 8;
#pragma unroll
        for (int t = 0; t < 8; t++) {
            int c = WN1 + t * 8 + tig * 2;
            __half2 p0 = __floats2half2_rn(acc[m][t][0] + sBias[c], acc[m][t][1] + sBias[c + 1]);
            __half2 p1 = __floats2half2_rn(acc[m][t][2] + sBias[c], acc[m][t][3] + sBias[c + 1]);
            *(uint32_t*)(sA + lr0 * LDA + c) = *(uint32_t*)&p0;
            *(uint32_t*)(sA + lr1 * LDA + c) = *(uint32_t*)&p1;
        }
    }
    __syncthreads();

    float acc2[2][4][4];
#pragma unroll
    for (int m = 0; m < 2; m++)
#pragma unroll
        for (int t = 0; t < 4; t++)
#pragma unroll
            for (int j = 0; j < 4; j++) acc2[m][t][j] = 0.f;

#pragma unroll
    for (int ks = 0; ks < 8; ks++) {
        uint32_t a0[4], a1[4];
        ldsm4(a0, uA + (uint32_t)(a0off + ks * 16) * 2);
        ldsm4(a1, uA + (uint32_t)(a1off + ks * 16) * 2);
#pragma unroll
        for (int p = 0; p < 2; p++) {
            int boff = (WN2 + p * 16 + bsel) * LDA + ks * 16 + bhalf * 8;
            uint32_t b[4];
            ldsm4(b, uB2 + (uint32_t)boff * 2);
            mma16816(acc2[0][2 * p],     a0, b);
            mma16816(acc2[0][2 * p + 1], a0, b + 2);
            mma16816(acc2[1][2 * p],     a1, b);
            mma16816(acc2[1][2 * p + 1], a1, b + 2);
        }
    }

#pragma unroll
    for (int m = 0; m < 2; m++) {
        int r0 = row0 + WM + m * 16 + gid;
        int r1 = r0 + 8;
#pragma unroll
        for (int t = 0; t < 4; t++) {
            int c = WN2 + t * 8 + tig * 2;
            int head = (WN2 >> 3) + t;
            float sl  = acc2[m][t][0] * sAS[c] + acc2[m][t][1] * sAS[c + 1];
            float shh = acc2[m][t][2] * sAS[c] + acc2[m][t][3] * sAS[c + 1];
            float dl  = acc2[m][t][0] * sAD[c] + acc2[m][t][1] * sAD[c + 1];
            float dhh = acc2[m][t][2] * sAD[c] + acc2[m][t][3] * sAD[c + 1];
#pragma unroll
            for (int o = 1; o < 4; o <<= 1) {
                sl  += __shfl_xor_sync(0xFFFFFFFFu, sl, o);
                shh += __shfl_xor_sync(0xFFFFFFFFu, shh, o);
                dl  += __shfl_xor_sync(0xFFFFFFFFu, dl, o);
                dhh += __shfl_xor_sync(0xFFFFFFFFu, dhh, o);
            }
            if (tig == 0) {
                if (r0 < M) { asrc[(size_t)r0 * 8 + head] = sl;  adst[(size_t)r0 * 8 + head] = dl; }
                if (r1 < M) { asrc[(size_t)r1 * 8 + head] = shh; adst[(size_t)r1 * 8 + head] = dhh; }
            }
            __half2 p0 = __floats2half2_rn(acc2[m][t][0], acc2[m][t][1]);
            __half2 p1 = __floats2half2_rn(acc2[m][t][2], acc2[m][t][3]);
            if (r0 < M) *(uint32_t*)(outh1 + (size_t)r0 * 64 + c) = *(uint32_t*)&p0;
            if (r1 < M) *(uint32_t*)(outh1 + (size_t)r1 * 64 + c) = *(uint32_t*)&p1;
        }
    }
}
#define SMEM_G12 ((128 + 128 + 64) * 136 * 2 + 128 * 4 + 64 * 8 + 256)

// ------------------- GEMM3: out[M,128] = aggh[M,64] @ W2 + b2 (fp32 out) -----
__global__ void __launch_bounds__(256) gemm3_kernel(
    const __half* __restrict__ Ag,
    const float* __restrict__ bias,
    float* __restrict__ out,
    int M)
{
    constexpr int K = 64, NC = 128, LDA = 72;
    const int tid = threadIdx.x;
    const int warp = tid >> 5;
    const int lane = tid & 31;
    const int gid = lane >> 2;
    const int tig = lane & 3;
    const int row0 = blockIdx.x * 128;
    const int WM = (warp & 3) * 32;
    const int WN = (warp >> 2) * 64;

    extern __shared__ char sm[];
    __half* sA = (__half*)sm;
    __half* sB = sA + 128 * LDA;
    float* sBias = (float*)(sB + NC * LDA);

    for (int idx = tid; idx < 128 * (K / 8); idx += 256) {
        int r = idx / (K / 8);
        int c = (idx % (K / 8)) * 8;
        int gr = row0 + r;
        uint4 v = make_uint4(0, 0, 0, 0);
        if (gr < M) v = *(const uint4*)(Ag + (size_t)gr * K + c);
        *(uint4*)(sA + r * LDA + c) = v;
    }
    for (int idx = tid; idx < NC * (K / 8); idx += 256) {
        int n = idx / (K / 8);
        int c = (idx % (K / 8)) * 8;
        *(uint4*)(sB + n * LDA + c) = *(const uint4*)(g_B3 + n * K + c);
    }
    if (tid < NC) sBias[tid] = bias[tid];
    __syncthreads();

    float acc[2][8][4];
#pragma unroll
    for (int m = 0; m < 2; m++)
#pragma unroll
        for (int t = 0; t < 8; t++)
#pragma unroll
            for (int j = 0; j < 4; j++) acc[m][t][j] = 0.f;

    const uint32_t uA = smem_u32(sA), uB = smem_u32(sB);
    const int a0off = (WM + (lane & 15)) * LDA + (lane >> 4) * 8;
    const int a1off = a0off + 16 * LDA;
    const int brow = lane & 7;
    const int bhalf = (lane >> 3) & 1;
    const int bsel = (lane >> 4) * 8 + brow;

#pragma unroll
    for (int ks = 0; ks < K / 16; ks++) {
        uint32_t a0[4], a1[4];
        ldsm4(a0, uA + (uint32_t)(a0off + ks * 16) * 2);
        ldsm4(a1, uA + (uint32_t)(a1off + ks * 16) * 2);
#pragma unroll
        for (int p = 0; p < 4; p++) {
            int boff = (WN + p * 16 + bsel) * LDA + ks * 16 + bhalf * 8;
            uint32_t b[4];
            ldsm4(b, uB + (uint32_t)boff * 2);
            mma16816(acc[0][2 * p],     a0, b);
            mma16816(acc[0][2 * p + 1], a0, b + 2);
            mma16816(acc[1][2 * p],     a1, b);
            mma16816(acc[1][2 * p + 1], a1, b + 2);
        }
    }

#pragma unroll
    for (int m = 0; m < 2; m++) {
        int r0 = row0 + WM + m * 16 + gid;
        int r1 = r0 + 8;
#pragma unroll
        for (int t = 0; t < 8; t++) {
            int c = WN + t * 8 + tig * 2;
            float b0 = sBias[c], b1v = sBias[c + 1];
            if (r0 < M) {
                float2 v = make_float2(acc[m][t][0] + b0, acc[m][t][1] + b1v);
                *(float2*)(out + (size_t)r0 * NC + c) = v;
            }
            if (r1 < M) {
                float2 v = make_float2(acc[m][t][2] + b0, acc[m][t][3] + b1v);
                *(float2*)(out + (size_t)r1 * NC + c) = v;
            }
        }
    }
}
#define SMEM_G3 ((128 + 128) * 72 * 2 + 128 * 4 + 256)

// ------------------- static init ---------------------------------------------
struct HxInit {
    cudaStream_t s2;
    cudaEvent_t evF, evJ;
    HxInit() {
        cudaStreamCreateWithFlags(&s2, cudaStreamNonBlocking);
        cudaEventCreateWithFlags(&evF, cudaEventDisableTiming);
        cudaEventCreateWithFlags(&evJ, cudaEventDisableTiming);
        cudaFuncSetAttribute(gemm12_kernel, cudaFuncAttributeMaxDynamicSharedMemorySize, SMEM_G12);
        cudaFuncSetAttribute(gemm3_kernel,  cudaFuncAttributeMaxDynamicSharedMemorySize, SMEM_G3);
    }
};
static HxInit g_hx;

// ------------------- CSR build (R8 configuration) -----------------------------
__global__ void init_kernel()
{
    int i = blockIdx.x * 256 + threadIdx.x;
    if (i < NN) { g_counts[i] = 1; g_cnt[i] = 0; }
}

__global__ void count_kernel(const int* __restrict__ dst)
{
    int e = blockIdx.x * 256 + threadIdx.x;
    if (e < EE) atomicAdd(&g_counts[dst[e]], 1);
}

__global__ void __launch_bounds__(1024) scan1_kernel()
{
    __shared__ int wsum[32];
    int tid = threadIdx.x, lane = tid & 31, wid = tid >> 5;
    int idx = blockIdx.x * 1024 + tid;
    int v = (idx < NN) ? g_counts[idx] : 0;
    int x = v;
#pragma unroll
    for (int off = 1; off < 32; off <<= 1) {
        int y = __shfl_up_sync(0xFFFFFFFFu, x, off);
        if (lane >= off) x += y;
    }
    if (lane == 31) wsum[wid] = x;
    __syncthreads();
    if (wid == 0) {
        int wv = wsum[lane];
#pragma unroll
        for (int off = 1; off < 32; off <<= 1) {
            int y = __shfl_up_sync(0xFFFFFFFFu, wv, off);
            if (lane >= off) wv += y;
        }
        wsum[lane] = wv;
    }
    __syncthreads();
    int pre = (wid > 0) ? wsum[wid - 1] : 0;
    if (idx < NN) g_rowoff[idx] = x + pre - v;
    if (tid == 1023) g_blocksum[blockIdx.x] = x + pre;
}

__global__ void __launch_bounds__(64) scan2_kernel(int nblocks)
{
    __shared__ int s0tot;
    int tid = threadIdx.x, lane = tid & 31, wid = tid >> 5;
    int v = (tid < nblocks) ? g_blocksum[tid] : 0;
    int x = v;
#pragma unroll
    for (int off = 1; off < 32; off <<= 1) {
        int y = __shfl_up_sync(0xFFFFFFFFu, x, off);
        if (lane >= off) x += y;
    }
    if (wid == 0 && lane == 31) s0tot = x;
    __syncthreads();
    int pre = (wid == 1) ? s0tot : 0;
    int excl = x - v + pre;
    if (tid < nblocks) g_blocksum[tid] = excl;
    if (tid == nblocks - 1) g_rowoff[NN] = excl + v;
}

__global__ void __launch_bounds__(1024) scan3_kernel()
{
    int idx = blockIdx.x * 1024 + threadIdx.x;
    if (idx < NN) g_rowoff[idx] += g_blocksum[blockIdx.x];
}

__global__ void scatter_kernel(const int* __restrict__ src, const int* __restrict__ dst)
{
    int e = blockIdx.x * 256 + threadIdx.x;
    if (e < EE) {
        int d = dst[e];
        int pos = g_rowoff[d] + atomicAdd(&g_cnt[d], 1);
        g_csrsrc[pos] = src[e];
    } else if (e < ET) {
        int i = e - EE;
        int pos = g_rowoff[i] + atomicAdd(&g_cnt[i], 1);
        g_csrsrc[pos] = i;
    }
}

// ------------------- GAT conv1 aggregation (+asrc2/adst2 epilogue) -----------
__global__ void __launch_bounds__(256) agg1_kernel(const float* __restrict__ b1)
{
    int w = (blockIdx.x * blockDim.x + threadIdx.x) >> 5;
    int lane = threadIdx.x & 31;
    if (w >= NN) return;
    int head = lane >> 2;
    int c0 = lane * 2;
    int beg = g_rowoff[w], end = g_rowoff[w + 1];

    float adh = g_adst1[w * 8 + head];

    float a0 = 0.f, a1 = 0.f, sA = 0.f;
    float p0b = 0.f, p1b = 0.f, sB = 0.f;
    float q0 = 0.f, q1 = 0.f, sC = 0.f;
    float r0 = 0.f, r1 = 0.f, sD = 0.f;
    int j = beg;
    for (; j + 4 <= end; j += 4) {
        int s0 = g_csrsrc[j], s1 = g_csrsrc[j + 1], s2 = g_csrsrc[j + 2], s3 = g_csrsrc[j + 3];
        float e0 = __expf(leaky(g_asrc1[s0 * 8 + head] + adh));
        float e1 = __expf(leaky(g_asrc1[s1 * 8 + head] + adh));
        float e2 = __expf(leaky(g_asrc1[s2 * 8 + head] + adh));
        float e3 = __expf(leaky(g_asrc1[s3 * 8 + head] + adh));
        float2 h0 = __half22float2(*(const __half2*)(g_h1h + s0 * 64 + c0));
        float2 h1v = __half22float2(*(const __half2*)(g_h1h + s1 * 64 + c0));
        float2 h2v = __half22float2(*(const __half2*)(g_h1h + s2 * 64 + c0));
        float2 h3v = __half22float2(*(const __half2*)(g_h1h + s3 * 64 + c0));
        a0 = fmaf(e0, h0.x, a0);  a1 = fmaf(e0, h0.y, a1);  sA += e0;
        p0b = fmaf(e1, h1v.x, p0b); p1b = fmaf(e1, h1v.y, p1b); sB += e1;
        q0 = fmaf(e2, h2v.x, q0); q1 = fmaf(e2, h2v.y, q1); sC += e2;
        r0 = fmaf(e3, h3v.x, r0); r1 = fmaf(e3, h3v.y, r1); sD += e3;
    }
    for (; j < end; j++) {
        int s = g_csrsrc[j];
        float e = __expf(leaky(g_asrc1[s * 8 + head] + adh));
        float2 hv = __half22float2(*(const __half2*)(g_h1h + s * 64 + c0));
        a0 = fmaf(e, hv.x, a0); a1 = fmaf(e, hv.y, a1); sA += e;
    }
    a0 += p0b + q0 + r0;
    a1 += p1b + q1 + r1;
    sA += sB + sC + sD;
    float inv = 1.f / sA;
    float o0 = a0 * inv + b1[c0];
    float o1 = a1 * inv + b1[c0 + 1];
    o0 = o0 > 0.f ? o0 : expm1f(o0);
    o1 = o1 > 0.f ? o1 : expm1f(o1);
    __half2 p = __floats2half2_rn(o0, o1);
    *(uint32_t*)(g_hm + w * 64 + c0) = *(uint32_t*)&p;

    // conv2 attention dots folded in: asrc2 = hm . (W2@attS2), adst2 = hm . (W2@attD2)
    float ps = o0 * g_wsd[c0] + o1 * g_wsd[c0 + 1];
    float pd = o0 * g_wsd[64 + c0] + o1 * g_wsd[64 + c0 + 1];
#pragma unroll
    for (int off = 16; off; off >>= 1) {
        ps += __shfl_xor_sync(0xFFFFFFFFu, ps, off);
        pd += __shfl_xor_sync(0xFFFFFFFFu, pd, off);
    }
    if (lane == 0) { g_asrc2[w] = ps; g_adst2[w] = pd; }
}

// ------------------- GAT conv2 aggregation over hm (64 ch, 128B/edge) --------
__global__ void __launch_bounds__(256) agg2_kernel()
{
    int w = (blockIdx.x * blockDim.x + threadIdx.x) >> 5;
    int lane = threadIdx.x & 31;
    if (w >= NN) return;
    int c0 = lane * 2;
    int beg = g_rowoff[w], end = g_rowoff[w + 1];
    float adh = g_adst2[w];

    float a0 = 0.f, a1 = 0.f, sA = 0.f;
    float p0b = 0.f, p1b = 0.f, sB = 0.f;
    float q0 = 0.f, q1 = 0.f, sC = 0.f;
    float r0 = 0.f, r1 = 0.f, sD = 0.f;
    int j = beg;
    for (; j + 4 <= end; j += 4) {
        int s0 = g_csrsrc[j], s1 = g_csrsrc[j + 1], s2 = g_csrsrc[j + 2], s3 = g_csrsrc[j + 3];
        float e0 = __expf(leaky(g_asrc2[s0] + adh));
        float e1 = __expf(leaky(g_asrc2[s1] + adh));
        float e2 = __expf(leaky(g_asrc2[s2] + adh));
        float e3 = __expf(leaky(g_asrc2[s3] + adh));
        float2 h0 = __half22float2(*(const __half2*)(g_hm + s0 * 64 + c0));
        float2 h1v = __half22float2(*(const __half2*)(g_hm + s1 * 64 + c0));
        float2 h2v = __half22float2(*(const __half2*)(g_hm + s2 * 64 + c0));
        float2 h3v = __half22float2(*(const __half2*)(g_hm + s3 * 64 + c0));
        a0 = fmaf(e0, h0.x, a0);  a1 = fmaf(e0, h0.y, a1);  sA += e0;
        p0b = fmaf(e1, h1v.x, p0b); p1b = fmaf(e1, h1v.y, p1b); sB += e1;
        q0 = fmaf(e2, h2v.x, q0); q1 = fmaf(e2, h2v.y, q1); sC += e2;
        r0 = fmaf(e3, h3v.x, r0); r1 = fmaf(e3, h3v.y, r1); sD += e3;
    }
    for (; j < end; j++) {
        int s = g_csrsrc[j];
        float e = __expf(leaky(g_asrc2[s] + adh));
        float2 hv = __half22float2(*(const __half2*)(g_hm + s * 64 + c0));
        a0 = fmaf(e, hv.x, a0); a1 = fmaf(e, hv.y, a1); sA += e;
    }
    a0 += p0b + q0 + r0;
    a1 += p1b + q1 + r1;
    sA += sB + sC + sD;
    float inv = 1.f / sA;
    __half2 p = __floats2half2_rn(a0 * inv, a1 * inv);
    *(uint32_t*)(g_aggh + w * 64 + c0) = *(uint32_t*)&p;
}

// ------------------- launch --------------------------------------------------
extern "C" void kernel_launch(void* const* d_in, const int* in_sizes, int n_in,
                              void* d_out, int out_size)
{
    (void)in_sizes; (void)n_in; (void)out_size;
    const float* x        = (const float*)d_in[0];
    const int*   ei       = (const int*)d_in[1];
    const float* W_map    = (const float*)d_in[2];
    const float* b_map    = (const float*)d_in[3];
    const float* W1       = (const float*)d_in[4];
    const float* att_src1 = (const float*)d_in[5];
    const float* att_dst1 = (const float*)d_in[6];
    const float* b1       = (const float*)d_in[7];
    const float* W2       = (const float*)d_in[8];
    const float* att_src2 = (const float*)d_in[9];
    const float* att_dst2 = (const float*)d_in[10];
    const float* b2       = (const float*)d_in[11];
    float* out = (float*)d_out;
    const int* src = ei;
    const int* dst = ei + EE;

    __half *p_h1h, *p_aggh;
    float *p_as1, *p_ad1;
    cudaGetSymbolAddress((void**)&p_h1h, g_h1h);
    cudaGetSymbolAddress((void**)&p_aggh, g_aggh);
    cudaGetSymbolAddress((void**)&p_as1, g_asrc1);
    cudaGetSymbolAddress((void**)&p_ad1, g_adst1);

    const int GEMM_BLOCKS = (NN + 127) / 128;
    const int N_BLOCKS    = (NN + 255) / 256;
    const int E_BLOCKS    = (EE + 255) / 256;
    const int ET_BLOCKS   = (ET + 255) / 256;
    const int WARP_BLOCKS = NN / 8;
    const int SCAN_BLOCKS = (NN + 1023) / 1024;

    cudaStream_t s2 = g_hx.s2;

    prep_w_kernel<<<129, 256>>>(W_map, W1, W2, att_src2, att_dst2);

    cudaEventRecord(g_hx.evF, 0);
    cudaStreamWaitEvent(s2, g_hx.evF, 0);
    init_kernel<<<N_BLOCKS, 256, 0, s2>>>();
    count_kernel<<<E_BLOCKS, 256, 0, s2>>>(dst);

    gemm12_kernel<<<GEMM_BLOCKS, 256, SMEM_G12>>>(
        x, b_map, att_src1, att_dst1, p_h1h, p_as1, p_ad1, NN);

    scan1_kernel<<<SCAN_BLOCKS, 1024, 0, s2>>>();
    scan2_kernel<<<1, 64, 0, s2>>>(SCAN_BLOCKS);
    scan3_kernel<<<SCAN_BLOCKS, 1024, 0, s2>>>();
    scatter_kernel<<<ET_BLOCKS, 256, 0, s2>>>(src, dst);
    cudaEventRecord(g_hx.evJ, s2);

    cudaStreamWaitEvent(0, g_hx.evJ, 0);

    agg1_kernel<<<WARP_BLOCKS, 256>>>(b1);
    agg2_kernel<<<WARP_BLOCKS, 256>>>();
    gemm3_kernel<<<GEMM_BLOCKS, 256, SMEM_G3>>>(p_aggh, b2, out, NN);
}

// round 11
// speedup vs baseline: 1.0741x; 1.0220x over previous
#include <cuda_runtime.h>
#include <cuda_fp16.h>
#include <math.h>
#include <stdint.h>

#define NN 50000
#define EE 1600000
#define ET (EE + NN)
#define FULLM 0xFFFFFFFFu

// ------------------- scratch (device globals; no allocation allowed) -------
__device__ __half g_h1h[NN * 64];
__device__ __half g_hm[NN * 64];     // conv1 output (post-ELU)
__device__ __half g_aggh[NN * 64];   // conv2 aggregated hm (pre-W2)
__device__ float g_asrc1[NN * 8];
__device__ float g_adst1[NN * 8];
__device__ float g_asrc2[NN];
__device__ float g_adst2[NN];
__device__ int   g_counts[NN];
__device__ int   g_rowoff[NN + 1];
__device__ int   g_csrsrc[ET];
__device__ int   g_erank[EE];
__device__ int   g_blocksum[64];
__device__ float g_wsd[128];         // [0:64) = W2@att_src2, [64:128) = W2@att_dst2
// pre-transposed fp16 weights: Bt[n][k] = W[k][n]
__device__ __half g_B1[128 * 128];   // W_map
__device__ __half g_B2[64 * 128];    // W1
__device__ __half g_B3[128 * 64];    // W2

__device__ __forceinline__ float leaky(float x) { return x > 0.f ? x : 0.2f * x; }

__device__ __forceinline__ uint32_t smem_u32(const void* p) {
    uint32_t a;
    asm("{ .reg .u64 t; cvta.to.shared.u64 t, %1; cvt.u32.u64 %0, t; }" : "=r"(a) : "l"(p));
    return a;
}
__device__ __forceinline__ void ldsm4(uint32_t* r, uint32_t addr) {
    asm volatile("ldmatrix.sync.aligned.m8n8.x4.shared.b16 {%0,%1,%2,%3}, [%4];"
        : "=r"(r[0]), "=r"(r[1]), "=r"(r[2]), "=r"(r[3]) : "r"(addr));
}
__device__ __forceinline__ void mma16816(float* d, const uint32_t* a, const uint32_t* b) {
    asm volatile(
        "mma.sync.aligned.m16n8k16.row.col.f32.f16.f16.f32 "
        "{%0,%1,%2,%3}, {%4,%5,%6,%7}, {%8,%9}, {%0,%1,%2,%3};"
        : "+f"(d[0]), "+f"(d[1]), "+f"(d[2]), "+f"(d[3])
        : "r"(a[0]), "r"(a[1]), "r"(a[2]), "r"(a[3]), "r"(b[0]), "r"(b[1]));
}

// ------------------- weight prep: transpose to fp16 + W2-folded att vectors --
__global__ void prep_w_kernel(const float* __restrict__ Wm, const float* __restrict__ W1,
                              const float* __restrict__ W2,
                              const float* __restrict__ attS2, const float* __restrict__ attD2)
{
    int i = blockIdx.x * 256 + threadIdx.x;
    if (i < 16384)      { int n = i >> 7, k = i & 127; g_B1[i] = __float2half(Wm[k * 128 + n]); }
    else if (i < 24576) { int j = i - 16384; int n = j >> 7, k = j & 127; g_B2[j] = __float2half(W1[k * 64 + n]); }
    else if (i < 32768) { int j = i - 24576; int n = j >> 6, k = j & 63;  g_B3[j] = __float2half(W2[k * 128 + n]); }
    else if (i < 32832) {
        int k = i - 32768;   // 0..63
        float s = 0.f, d = 0.f;
        const float* row = W2 + k * 128;
#pragma unroll 4
        for (int n = 0; n < 128; n++) {
            s = fmaf(row[n], attS2[n], s);
            d = fmaf(row[n], attD2[n], d);
        }
        g_wsd[k] = s;
        g_wsd[64 + k] = d;
    }
}

// ------------------- fused GEMM1+GEMM2 (+att1): x -> h1, asrc1, adst1 --------
__global__ void __launch_bounds__(256, 2) gemm12_kernel(
    const float* __restrict__ A32,
    const float* __restrict__ bias,
    const float* __restrict__ attS, const float* __restrict__ attD,
    __half* __restrict__ outh1,
    float* __restrict__ asrc, float* __restrict__ adst,
    int M)
{
    constexpr int LDA = 136;
    const int tid = threadIdx.x;
    const int warp = tid >> 5;
    const int lane = tid & 31;
    const int gid = lane >> 2;
    const int tig = lane & 3;
    const int row0 = blockIdx.x * 128;
    const int WM = (warp & 3) * 32;
    const int WN1 = (warp >> 2) * 64;
    const int WN2 = (warp >> 2) * 32;

    extern __shared__ char sm[];
    __half* sA  = (__half*)sm;
    __half* sB1 = sA + 128 * LDA;
    __half* sB2 = sB1 + 128 * LDA;
    float* sBias = (float*)(sB2 + 64 * LDA);
    float* sAS = sBias + 128;
    float* sAD = sAS + 64;

    for (int idx = tid; idx < 128 * 32; idx += 256) {
        int r = idx >> 5;
        int c = (idx & 31) * 4;
        int gr = row0 + r;
        float4 v = make_float4(0.f, 0.f, 0.f, 0.f);
        if (gr < M) v = *(const float4*)(A32 + (size_t)gr * 128 + c);
        __half2 p0 = __floats2half2_rn(v.x, v.y);
        __half2 p1 = __floats2half2_rn(v.z, v.w);
        *(uint2*)(sA + r * LDA + c) = make_uint2(*(uint32_t*)&p0, *(uint32_t*)&p1);
    }
    for (int idx = tid; idx < 128 * 16; idx += 256) {
        int n = idx >> 4;
        int c = (idx & 15) * 8;
        *(uint4*)(sB1 + n * LDA + c) = *(const uint4*)(g_B1 + n * 128 + c);
    }
    for (int idx = tid; idx < 64 * 16; idx += 256) {
        int n = idx >> 4;
        int c = (idx & 15) * 8;
        *(uint4*)(sB2 + n * LDA + c) = *(const uint4*)(g_B2 + n * 128 + c);
    }
    if (tid < 128) sBias[tid] = bias[tid];
    if (tid < 64) { sAS[tid] = attS[tid]; sAD[tid] = attD[tid]; }
    __syncthreads();

    const uint32_t uA = smem_u32(sA), uB1 = smem_u32(sB1), uB2 = smem_u32(sB2);
    const int a0off = (WM + (lane & 15)) * LDA + (lane >> 4) * 8;
    const int a1off = a0off + 16 * LDA;
    const int brow = lane & 7;
    const int bhalf = (lane >> 3) & 1;
    const int bsel = (lane >> 4) * 8 + brow;

    float acc[2][8][4];
#pragma unroll
    for (int m = 0; m < 2; m++)
#pragma unroll
        for (int t = 0; t < 8; t++)
#pragma unroll
            for (int j = 0; j < 4; j++) acc[m][t][j] = 0.f;

#pragma unroll
    for (int ks = 0; ks < 8; ks++) {
        uint32_t a0[4], a1[4];
        ldsm4(a0, uA + (uint32_t)(a0off + ks * 16) * 2);
        ldsm4(a1, uA + (uint32_t)(a1off + ks * 16) * 2);
#pragma unroll
        for (int p = 0; p < 4; p++) {
            int boff = (WN1 + p * 16 + bsel) * LDA + ks * 16 + bhalf * 8;
            uint32_t b[4];
            ldsm4(b, uB1 + (uint32_t)boff * 2);
            mma16816(acc[0][2 * p],     a0, b);
            mma16816(acc[0][2 * p + 1], a0, b + 2);
            mma16816(acc[1][2 * p],     a1, b);
            mma16816(acc[1][2 * p + 1], a1, b + 2);
        }
    }
    __syncthreads();

#pragma unroll
    for (int m = 0; m < 2; m++) {
        int lr0 = WM + m * 16 + gid;
        int lr1 = lr0 + 8;
#pragma unroll
        for (int t = 0; t < 8; t++) {
            int c = WN1 + t * 8 + tig * 2;
            __half2 p0 = __floats2half2_rn(acc[m][t][0] + sBias[c], acc[m][t][1] + sBias[c + 1]);
            __half2 p1 = __floats2half2_rn(acc[m][t][2] + sBias[c], acc[m][t][3] + sBias[c + 1]);
            *(uint32_t*)(sA + lr0 * LDA + c) = *(uint32_t*)&p0;
            *(uint32_t*)(sA + lr1 * LDA + c) = *(uint32_t*)&p1;
        }
    }
    __syncthreads();

    float acc2[2][4][4];
#pragma unroll
    for (int m = 0; m < 2; m++)
#pragma unroll
        for (int t = 0; t < 4; t++)
#pragma unroll
            for (int j = 0; j < 4; j++) acc2[m][t][j] = 0.f;

#pragma unroll
    for (int ks = 0; ks < 8; ks++) {
        uint32_t a0[4], a1[4];
        ldsm4(a0, uA + (uint32_t)(a0off + ks * 16) * 2);
        ldsm4(a1, uA + (uint32_t)(a1off + ks * 16) * 2);
#pragma unroll
        for (int p = 0; p < 2; p++) {
            int boff = (WN2 + p * 16 + bsel) * LDA + ks * 16 + bhalf * 8;
            uint32_t b[4];
            ldsm4(b, uB2 + (uint32_t)boff * 2);
            mma16816(acc2[0][2 * p],     a0, b);
            mma16816(acc2[0][2 * p + 1], a0, b + 2);
            mma16816(acc2[1][2 * p],     a1, b);
            mma16816(acc2[1][2 * p + 1], a1, b + 2);
        }
    }

#pragma unroll
    for (int m = 0; m < 2; m++) {
        int r0 = row0 + WM + m * 16 + gid;
        int r1 = r0 + 8;
#pragma unroll
        for (int t = 0; t < 4; t++) {
            int c = WN2 + t * 8 + tig * 2;
            int head = (WN2 >> 3) + t;
            float sl  = acc2[m][t][0] * sAS[c] + acc2[m][t][1] * sAS[c + 1];
            float shh = acc2[m][t][2] * sAS[c] + acc2[m][t][3] * sAS[c + 1];
            float dl  = acc2[m][t][0] * sAD[c] + acc2[m][t][1] * sAD[c + 1];
            float dhh = acc2[m][t][2] * sAD[c] + acc2[m][t][3] * sAD[c + 1];
#pragma unroll
            for (int o = 1; o < 4; o <<= 1) {
                sl  += __shfl_xor_sync(FULLM, sl, o);
                shh += __shfl_xor_sync(FULLM, shh, o);
                dl  += __shfl_xor_sync(FULLM, dl, o);
                dhh += __shfl_xor_sync(FULLM, dhh, o);
            }
            if (tig == 0) {
                if (r0 < M) { asrc[(size_t)r0 * 8 + head] = sl;  adst[(size_t)r0 * 8 + head] = dl; }
                if (r1 < M) { asrc[(size_t)r1 * 8 + head] = shh; adst[(size_t)r1 * 8 + head] = dhh; }
            }
            __half2 p0 = __floats2half2_rn(acc2[m][t][0], acc2[m][t][1]);
            __half2 p1 = __floats2half2_rn(acc2[m][t][2], acc2[m][t][3]);
            if (r0 < M) *(uint32_t*)(outh1 + (size_t)r0 * 64 + c) = *(uint32_t*)&p0;
            if (r1 < M) *(uint32_t*)(outh1 + (size_t)r1 * 64 + c) = *(uint32_t*)&p1;
        }
    }
}
#define SMEM_G12 ((128 + 128 + 64) * 136 * 2 + 128 * 4 + 64 * 8 + 256)

// ------------------- GEMM3: out[M,128] = aggh[M,64] @ W2 + b2 (fp32 out) -----
__global__ void __launch_bounds__(256) gemm3_kernel(
    const __half* __restrict__ Ag,
    const float* __restrict__ bias,
    float* __restrict__ out,
    int M)
{
    constexpr int K = 64, NC = 128, LDA = 72;
    const int tid = threadIdx.x;
    const int warp = tid >> 5;
    const int lane = tid & 31;
    const int gid = lane >> 2;
    const int tig = lane & 3;
    const int row0 = blockIdx.x * 128;
    const int WM = (warp & 3) * 32;
    const int WN = (warp >> 2) * 64;

    extern __shared__ char sm[];
    __half* sA = (__half*)sm;
    __half* sB = sA + 128 * LDA;
    float* sBias = (float*)(sB + NC * LDA);

    for (int idx = tid; idx < 128 * (K / 8); idx += 256) {
        int r = idx / (K / 8);
        int c = (idx % (K / 8)) * 8;
        int gr = row0 + r;
        uint4 v = make_uint4(0, 0, 0, 0);
        if (gr < M) v = *(const uint4*)(Ag + (size_t)gr * K + c);
        *(uint4*)(sA + r * LDA + c) = v;
    }
    for (int idx = tid; idx < NC * (K / 8); idx += 256) {
        int n = idx / (K / 8);
        int c = (idx % (K / 8)) * 8;
        *(uint4*)(sB + n * LDA + c) = *(const uint4*)(g_B3 + n * K + c);
    }
    if (tid < NC) sBias[tid] = bias[tid];
    __syncthreads();

    float acc[2][8][4];
#pragma unroll
    for (int m = 0; m < 2; m++)
#pragma unroll
        for (int t = 0; t < 8; t++)
#pragma unroll
            for (int j = 0; j < 4; j++) acc[m][t][j] = 0.f;

    const uint32_t uA = smem_u32(sA), uB = smem_u32(sB);
    const int a0off = (WM + (lane & 15)) * LDA + (lane >> 4) * 8;
    const int a1off = a0off + 16 * LDA;
    const int brow = lane & 7;
    const int bhalf = (lane >> 3) & 1;
    const int bsel = (lane >> 4) * 8 + brow;

#pragma unroll
    for (int ks = 0; ks < K / 16; ks++) {
        uint32_t a0[4], a1[4];
        ldsm4(a0, uA + (uint32_t)(a0off + ks * 16) * 2);
        ldsm4(a1, uA + (uint32_t)(a1off + ks * 16) * 2);
#pragma unroll
        for (int p = 0; p < 4; p++) {
            int boff = (WN + p * 16 + bsel) * LDA + ks * 16 + bhalf * 8;
            uint32_t b[4];
            ldsm4(b, uB + (uint32_t)boff * 2);
            mma16816(acc[0][2 * p],     a0, b);
            mma16816(acc[0][2 * p + 1], a0, b + 2);
            mma16816(acc[1][2 * p],     a1, b);
            mma16816(acc[1][2 * p + 1], a1, b + 2);
        }
    }

#pragma unroll
    for (int m = 0; m < 2; m++) {
        int r0 = row0 + WM + m * 16 + gid;
        int r1 = r0 + 8;
#pragma unroll
        for (int t = 0; t < 8; t++) {
            int c = WN + t * 8 + tig * 2;
            float b0 = sBias[c], b1v = sBias[c + 1];
            if (r0 < M) {
                float2 v = make_float2(acc[m][t][0] + b0, acc[m][t][1] + b1v);
                *(float2*)(out + (size_t)r0 * NC + c) = v;
            }
            if (r1 < M) {
                float2 v = make_float2(acc[m][t][2] + b0, acc[m][t][3] + b1v);
                *(float2*)(out + (size_t)r1 * NC + c) = v;
            }
        }
    }
}
#define SMEM_G3 ((128 + 128) * 72 * 2 + 128 * 4 + 256)

// ------------------- static init ---------------------------------------------
struct HxInit {
    cudaStream_t s2;
    cudaEvent_t evF, evJ;
    HxInit() {
        cudaStreamCreateWithFlags(&s2, cudaStreamNonBlocking);
        cudaEventCreateWithFlags(&evF, cudaEventDisableTiming);
        cudaEventCreateWithFlags(&evJ, cudaEventDisableTiming);
        cudaFuncSetAttribute(gemm12_kernel, cudaFuncAttributeMaxDynamicSharedMemorySize, SMEM_G12);
        cudaFuncSetAttribute(gemm3_kernel,  cudaFuncAttributeMaxDynamicSharedMemorySize, SMEM_G3);
    }
};
static HxInit g_hx;

// ------------------- CSR build (rank-based, atomic-free scatter) -------------
__global__ void init_kernel()
{
    int i = blockIdx.x * 256 + threadIdx.x;
    if (i < NN) g_counts[i] = 1;   // slot 0 reserved for self loop
}

// count + record per-edge rank within its destination row
__global__ void count_kernel(const int* __restrict__ dst)
{
    int e = blockIdx.x * 256 + threadIdx.x;
    if (e < EE) g_erank[e] = atomicAdd(&g_counts[dst[e]], 1);
}

__global__ void __launch_bounds__(1024) scan1_kernel()
{
    __shared__ int wsum[32];
    int tid = threadIdx.x, lane = tid & 31, wid = tid >> 5;
    int idx = blockIdx.x * 1024 + tid;
    int v = (idx < NN) ? g_counts[idx] : 0;
    int x = v;
#pragma unroll
    for (int off = 1; off < 32; off <<= 1) {
        int y = __shfl_up_sync(FULLM, x, off);
        if (lane >= off) x += y;
    }
    if (lane == 31) wsum[wid] = x;
    __syncthreads();
    if (wid == 0) {
        int wv = wsum[lane];
#pragma unroll
        for (int off = 1; off < 32; off <<= 1) {
            int y = __shfl_up_sync(FULLM, wv, off);
            if (lane >= off) wv += y;
        }
        wsum[lane] = wv;
    }
    __syncthreads();
    int pre = (wid > 0) ? wsum[wid - 1] : 0;
    if (idx < NN) g_rowoff[idx] = x + pre - v;
    if (tid == 1023) g_blocksum[blockIdx.x] = x + pre;
}

__global__ void __launch_bounds__(64) scan2_kernel(int nblocks)
{
    __shared__ int s0tot;
    int tid = threadIdx.x, lane = tid & 31, wid = tid >> 5;
    int v = (tid < nblocks) ? g_blocksum[tid] : 0;
    int x = v;
#pragma unroll
    for (int off = 1; off < 32; off <<= 1) {
        int y = __shfl_up_sync(FULLM, x, off);
        if (lane >= off) x += y;
    }
    if (wid == 0 && lane == 31) s0tot = x;
    __syncthreads();
    int pre = (wid == 1) ? s0tot : 0;
    int excl = x - v + pre;
    if (tid < nblocks) g_blocksum[tid] = excl;
    if (tid == nblocks - 1) g_rowoff[NN] = excl + v;
}

// adds block offsets + writes self-loop entry at slot 0 of each row
__global__ void __launch_bounds__(1024) scan3_kernel()
{
    int idx = blockIdx.x * 1024 + threadIdx.x;
    if (idx < NN) {
        int off = g_rowoff[idx] + g_blocksum[blockIdx.x];
        g_rowoff[idx] = off;
        g_csrsrc[off] = idx;    // self loop
    }
}

// pure load/store scatter: pos = rowoff[dst] + rank (no atomics)
__global__ void scatter_kernel(const int* __restrict__ src, const int* __restrict__ dst)
{
    int e = blockIdx.x * 256 + threadIdx.x;
    if (e < EE) {
        int d = dst[e];
        g_csrsrc[g_rowoff[d] + g_erank[e]] = src[e];
    }
}

// ------------------- GAT conv1 aggregation (warp-staged idx, +conv2 att dots)
__global__ void __launch_bounds__(256) agg1_kernel(const float* __restrict__ b1)
{
    int w = (blockIdx.x * blockDim.x + threadIdx.x) >> 5;
    int lane = threadIdx.x & 31;
    if (w >= NN) return;
    int head = lane >> 2;
    int c0 = lane * 2;
    int beg = g_rowoff[w], end = g_rowoff[w + 1];
    float adh = g_adst1[w * 8 + head];

    float a0 = 0.f, a1 = 0.f, sSum = 0.f;
    float b0a = 0.f, b1a = 0.f;
    float c0a = 0.f, c1a = 0.f;
    float d0a = 0.f, d1a = 0.f;

    for (int base = beg; base < end; base += 32) {
        int n = end - base;
        int kmax = n < 32 ? n : 32;
        int sl = (lane < kmax) ? g_csrsrc[base + lane] : 0;
        int k = 0;
        for (; k + 4 <= kmax; k += 4) {
            int s0 = __shfl_sync(FULLM, sl, k);
            int s1 = __shfl_sync(FULLM, sl, k + 1);
            int s2 = __shfl_sync(FULLM, sl, k + 2);
            int s3 = __shfl_sync(FULLM, sl, k + 3);
            float e0 = __expf(leaky(g_asrc1[s0 * 8 + head] + adh));
            float e1 = __expf(leaky(g_asrc1[s1 * 8 + head] + adh));
            float e2 = __expf(leaky(g_asrc1[s2 * 8 + head] + adh));
            float e3 = __expf(leaky(g_asrc1[s3 * 8 + head] + adh));
            float2 h0 = __half22float2(*(const __half2*)(g_h1h + s0 * 64 + c0));
            float2 h1 = __half22float2(*(const __half2*)(g_h1h + s1 * 64 + c0));
            float2 h2 = __half22float2(*(const __half2*)(g_h1h + s2 * 64 + c0));
            float2 h3 = __half22float2(*(const __half2*)(g_h1h + s3 * 64 + c0));
            a0 = fmaf(e0, h0.x, a0);  a1 = fmaf(e0, h0.y, a1);
            b0a = fmaf(e1, h1.x, b0a); b1a = fmaf(e1, h1.y, b1a);
            c0a = fmaf(e2, h2.x, c0a); c1a = fmaf(e2, h2.y, c1a);
            d0a = fmaf(e3, h3.x, d0a); d1a = fmaf(e3, h3.y, d1a);
            sSum += e0 + e1 + e2 + e3;
        }
        for (; k < kmax; k++) {
            int s = __shfl_sync(FULLM, sl, k);
            float e = __expf(leaky(g_asrc1[s * 8 + head] + adh));
            float2 hv = __half22float2(*(const __half2*)(g_h1h + s * 64 + c0));
            a0 = fmaf(e, hv.x, a0); a1 = fmaf(e, hv.y, a1);
            sSum += e;
        }
    }
    a0 += b0a + c0a + d0a;
    a1 += b1a + c1a + d1a;
    float inv = 1.f / sSum;
    float o0 = a0 * inv + b1[c0];
    float o1 = a1 * inv + b1[c0 + 1];
    o0 = o0 > 0.f ? o0 : expm1f(o0);
    o1 = o1 > 0.f ? o1 : expm1f(o1);
    __half2 p = __floats2half2_rn(o0, o1);
    *(uint32_t*)(g_hm + w * 64 + c0) = *(uint32_t*)&p;

    // conv2 attention dots folded in
    float ps = o0 * g_wsd[c0] + o1 * g_wsd[c0 + 1];
    float pd = o0 * g_wsd[64 + c0] + o1 * g_wsd[64 + c0 + 1];
#pragma unroll
    for (int off = 16; off; off >>= 1) {
        ps += __shfl_xor_sync(FULLM, ps, off);
        pd += __shfl_xor_sync(FULLM, pd, off);
    }
    if (lane == 0) { g_asrc2[w] = ps; g_adst2[w] = pd; }
}

// ------------------- GAT conv2 aggregation (lane-parallel weights) -----------
__global__ void __launch_bounds__(256) agg2_kernel()
{
    int w = (blockIdx.x * blockDim.x + threadIdx.x) >> 5;
    int lane = threadIdx.x & 31;
    if (w >= NN) return;
    int c0 = lane * 2;
    int beg = g_rowoff[w], end = g_rowoff[w + 1];
    float adh = g_adst2[w];

    float a0 = 0.f, a1 = 0.f, sSum = 0.f;
    float b0a = 0.f, b1a = 0.f;
    float c0a = 0.f, c1a = 0.f;
    float d0a = 0.f, d1a = 0.f;

    for (int base = beg; base < end; base += 32) {
        int n = end - base;
        int kmax = n < 32 ? n : 32;
        int sl = 0;
        float el = 0.f;
        if (lane < kmax) {
            sl = g_csrsrc[base + lane];
            el = __expf(leaky(g_asrc2[sl] + adh));
        }
        sSum += el;     // lane-partial sum of weights
        int k = 0;
        for (; k + 4 <= kmax; k += 4) {
            int s0 = __shfl_sync(FULLM, sl, k);
            int s1 = __shfl_sync(FULLM, sl, k + 1);
            int s2 = __shfl_sync(FULLM, sl, k + 2);
            int s3 = __shfl_sync(FULLM, sl, k + 3);
            float e0 = __shfl_sync(FULLM, el, k);
            float e1 = __shfl_sync(FULLM, el, k + 1);
            float e2 = __shfl_sync(FULLM, el, k + 2);
            float e3 = __shfl_sync(FULLM, el, k + 3);
            float2 h0 = __half22float2(*(const __half2*)(g_hm + s0 * 64 + c0));
            float2 h1 = __half22float2(*(const __half2*)(g_hm + s1 * 64 + c0));
            float2 h2 = __half22float2(*(const __half2*)(g_hm + s2 * 64 + c0));
            float2 h3 = __half22float2(*(const __half2*)(g_hm + s3 * 64 + c0));
            a0 = fmaf(e0, h0.x, a0);  a1 = fmaf(e0, h0.y, a1);
            b0a = fmaf(e1, h1.x, b0a); b1a = fmaf(e1, h1.y, b1a);
            c0a = fmaf(e2, h2.x, c0a); c1a = fmaf(e2, h2.y, c1a);
            d0a = fmaf(e3, h3.x, d0a); d1a = fmaf(e3, h3.y, d1a);
        }
        for (; k < kmax; k++) {
            int s = __shfl_sync(FULLM, sl, k);
            float e = __shfl_sync(FULLM, el, k);
            float2 hv = __half22float2(*(const __half2*)(g_hm + s * 64 + c0));
            a0 = fmaf(e, hv.x, a0); a1 = fmaf(e, hv.y, a1);
        }
    }
    a0 += b0a + c0a + d0a;
    a1 += b1a + c1a + d1a;
    // total weight sum across lanes
#pragma unroll
    for (int off = 16; off; off >>= 1)
        sSum += __shfl_xor_sync(FULLM, sSum, off);
    float inv = 1.f / sSum;
    __half2 p = __floats2half2_rn(a0 * inv, a1 * inv);
    *(uint32_t*)(g_aggh + w * 64 + c0) = *(uint32_t*)&p;
}

// ------------------- launch --------------------------------------------------
extern "C" void kernel_launch(void* const* d_in, const int* in_sizes, int n_in,
                              void* d_out, int out_size)
{
    (void)in_sizes; (void)n_in; (void)out_size;
    const float* x        = (const float*)d_in[0];
    const int*   ei       = (const int*)d_in[1];
    const float* W_map    = (const float*)d_in[2];
    const float* b_map    = (const float*)d_in[3];
    const float* W1       = (const float*)d_in[4];
    const float* att_src1 = (const float*)d_in[5];
    const float* att_dst1 = (const float*)d_in[6];
    const float* b1       = (const float*)d_in[7];
    const float* W2       = (const float*)d_in[8];
    const float* att_src2 = (const float*)d_in[9];
    const float* att_dst2 = (const float*)d_in[10];
    const float* b2       = (const float*)d_in[11];
    float* out = (float*)d_out;
    const int* src = ei;
    const int* dst = ei + EE;

    __half *p_h1h, *p_aggh;
    float *p_as1, *p_ad1;
    cudaGetSymbolAddress((void**)&p_h1h, g_h1h);
    cudaGetSymbolAddress((void**)&p_aggh, g_aggh);
    cudaGetSymbolAddress((void**)&p_as1, g_asrc1);
    cudaGetSymbolAddress((void**)&p_ad1, g_adst1);

    const int GEMM_BLOCKS = (NN + 127) / 128;
    const int N_BLOCKS    = (NN + 255) / 256;
    const int E_BLOCKS    = (EE + 255) / 256;
    const int WARP_BLOCKS = NN / 8;
    const int SCAN_BLOCKS = (NN + 1023) / 1024;

    cudaStream_t s2 = g_hx.s2;

    prep_w_kernel<<<129, 256>>>(W_map, W1, W2, att_src2, att_dst2);

    cudaEventRecord(g_hx.evF, 0);
    cudaStreamWaitEvent(s2, g_hx.evF, 0);
    init_kernel<<<N_BLOCKS, 256, 0, s2>>>();
    count_kernel<<<E_BLOCKS, 256, 0, s2>>>(dst);

    gemm12_kernel<<<GEMM_BLOCKS, 256, SMEM_G12>>>(
        x, b_map, att_src1, att_dst1, p_h1h, p_as1, p_ad1, NN);

    scan1_kernel<<<SCAN_BLOCKS, 1024, 0, s2>>>();
    scan2_kernel<<<1, 64, 0, s2>>>(SCAN_BLOCKS);
    scan3_kernel<<<SCAN_BLOCKS, 1024, 0, s2>>>();
    scatter_kernel<<<E_BLOCKS, 256, 0, s2>>>(src, dst);
    cudaEventRecord(g_hx.evJ, s2);

    cudaStreamWaitEvent(0, g_hx.evJ, 0);

    agg1_kernel<<<WARP_BLOCKS, 256>>>(b1);
    agg2_kernel<<<WARP_BLOCKS, 256>>>();
    gemm3_kernel<<<GEMM_BLOCKS, 256, SMEM_G3>>>(p_aggh, b2, out, NN);
}

// round 13
// speedup vs baseline: 1.1293x; 1.0513x over previous
#include <cuda_runtime.h>
#include <cuda_fp16.h>
#include <math.h>
#include <stdint.h>

#define NN 50000
#define EE 1600000
#define ET (EE + NN)
#define FULLM 0xFFFFFFFFu

// ------------------- scratch (device globals; no allocation allowed) -------
__device__ __half g_h1h[NN * 64];
__device__ __half g_hm[NN * 64];
__device__ __half g_aggh[NN * 64];
__device__ float g_asrc1[NN * 8];
__device__ float g_adst1[NN * 8];
__device__ float g_asrc2[NN];
__device__ float g_adst2[NN];
__device__ int   g_counts[NN];
__device__ int   g_rowoff[NN + 1];
__device__ int   g_csrsrc[ET];
__device__ int   g_erank[EE];
__device__ int   g_blocksum[64];
__device__ float g_wsd[128];
// pre-transposed fp16 weights: Bt[n][k] = W[k][n]
__device__ __half g_B1[128 * 128];
__device__ __half g_B2[64 * 128];
__device__ __half g_B3[128 * 64];

__device__ __forceinline__ float leaky(float x) { return x > 0.f ? x : 0.2f * x; }

__device__ __forceinline__ uint32_t smem_u32(const void* p) {
    uint32_t a;
    asm("{ .reg .u64 t; cvta.to.shared.u64 t, %1; cvt.u32.u64 %0, t; }" : "=r"(a) : "l"(p));
    return a;
}
__device__ __forceinline__ void ldsm4(uint32_t* r, uint32_t addr) {
    asm volatile("ldmatrix.sync.aligned.m8n8.x4.shared.b16 {%0,%1,%2,%3}, [%4];"
        : "=r"(r[0]), "=r"(r[1]), "=r"(r[2]), "=r"(r[3]) : "r"(addr));
}
__device__ __forceinline__ void mma16816(float* d, const uint32_t* a, const uint32_t* b) {
    asm volatile(
        "mma.sync.aligned.m16n8k16.row.col.f32.f16.f16.f32 "
        "{%0,%1,%2,%3}, {%4,%5,%6,%7}, {%8,%9}, {%0,%1,%2,%3};"
        : "+f"(d[0]), "+f"(d[1]), "+f"(d[2]), "+f"(d[3])
        : "r"(a[0]), "r"(a[1]), "r"(a[2]), "r"(a[3]), "r"(b[0]), "r"(b[1]));
}

// ------------------- weight prep ---------------------------------------------
__global__ void prep_w_kernel(const float* __restrict__ Wm, const float* __restrict__ W1,
                              const float* __restrict__ W2,
                              const float* __restrict__ attS2, const float* __restrict__ attD2)
{
    int i = blockIdx.x * 256 + threadIdx.x;
    if (i < 16384)      { int n = i >> 7, k = i & 127; g_B1[i] = __float2half(Wm[k * 128 + n]); }
    else if (i < 24576) { int j = i - 16384; int n = j >> 7, k = j & 127; g_B2[j] = __float2half(W1[k * 64 + n]); }
    else if (i < 32768) { int j = i - 24576; int n = j >> 6, k = j & 63;  g_B3[j] = __float2half(W2[k * 128 + n]); }
    else if (i < 32832) {
        int k = i - 32768;
        float s = 0.f, d = 0.f;
        const float* row = W2 + k * 128;
#pragma unroll 4
        for (int n = 0; n < 128; n++) {
            s = fmaf(row[n], attS2[n], s);
            d = fmaf(row[n], attD2[n], d);
        }
        g_wsd[k] = s;
        g_wsd[64 + k] = d;
    }
}

// ------------------- fused GEMM1+GEMM2 (+att1) --------------------------------
__global__ void __launch_bounds__(256, 2) gemm12_kernel(
    const float* __restrict__ A32,
    const float* __restrict__ bias,
    const float* __restrict__ attS, const float* __restrict__ attD,
    __half* __restrict__ outh1,
    float* __restrict__ asrc, float* __restrict__ adst,
    int M)
{
    constexpr int LDA = 136;
    const int tid = threadIdx.x;
    const int warp = tid >> 5;
    const int lane = tid & 31;
    const int gid = lane >> 2;
    const int tig = lane & 3;
    const int row0 = blockIdx.x * 128;
    const int WM = (warp & 3) * 32;
    const int WN1 = (warp >> 2) * 64;
    const int WN2 = (warp >> 2) * 32;

    extern __shared__ char sm[];
    __half* sA  = (__half*)sm;
    __half* sB1 = sA + 128 * LDA;
    __half* sB2 = sB1 + 128 * LDA;
    float* sBias = (float*)(sB2 + 64 * LDA);
    float* sAS = sBias + 128;
    float* sAD = sAS + 64;

    for (int idx = tid; idx < 128 * 32; idx += 256) {
        int r = idx >> 5;
        int c = (idx & 31) * 4;
        int gr = row0 + r;
        float4 v = make_float4(0.f, 0.f, 0.f, 0.f);
        if (gr < M) v = *(const float4*)(A32 + (size_t)gr * 128 + c);
        __half2 p0 = __floats2half2_rn(v.x, v.y);
        __half2 p1 = __floats2half2_rn(v.z, v.w);
        *(uint2*)(sA + r * LDA + c) = make_uint2(*(uint32_t*)&p0, *(uint32_t*)&p1);
    }
    for (int idx = tid; idx < 128 * 16; idx += 256) {
        int n = idx >> 4;
        int c = (idx & 15) * 8;
        *(uint4*)(sB1 + n * LDA + c) = *(const uint4*)(g_B1 + n * 128 + c);
    }
    for (int idx = tid; idx < 64 * 16; idx += 256) {
        int n = idx >> 4;
        int c = (idx & 15) * 8;
        *(uint4*)(sB2 + n * LDA + c) = *(const uint4*)(g_B2 + n * 128 + c);
    }
    if (tid < 128) sBias[tid] = bias[tid];
    if (tid < 64) { sAS[tid] = attS[tid]; sAD[tid] = attD[tid]; }
    __syncthreads();

    const uint32_t uA = smem_u32(sA), uB1 = smem_u32(sB1), uB2 = smem_u32(sB2);
    const int a0off = (WM + (lane & 15)) * LDA + (lane >> 4) * 8;
    const int a1off = a0off + 16 * LDA;
    const int brow = lane & 7;
    const int bhalf = (lane >> 3) & 1;
    const int bsel = (lane >> 4) * 8 + brow;

    float acc[2][8][4];
#pragma unroll
    for (int m = 0; m < 2; m++)
#pragma unroll
        for (int t = 0; t < 8; t++)
#pragma unroll
            for (int j = 0; j < 4; j++) acc[m][t][j] = 0.f;

#pragma unroll
    for (int ks = 0; ks < 8; ks++) {
        uint32_t a0[4], a1[4];
        ldsm4(a0, uA + (uint32_t)(a0off + ks * 16) * 2);
        ldsm4(a1, uA + (uint32_t)(a1off + ks * 16) * 2);
#pragma unroll
        for (int p = 0; p < 4; p++) {
            int boff = (WN1 + p * 16 + bsel) * LDA + ks * 16 + bhalf * 8;
            uint32_t b[4];
            ldsm4(b, uB1 + (uint32_t)boff * 2);
            mma16816(acc[0][2 * p],     a0, b);
            mma16816(acc[0][2 * p + 1], a0, b + 2);
            mma16816(acc[1][2 * p],     a1, b);
            mma16816(acc[1][2 * p + 1], a1, b + 2);
        }
    }
    __syncthreads();

#pragma unroll
    for (int m = 0; m < 2; m++) {
        int lr0 = WM + m * 16 + gid;
        int lr1 = lr0 + 8;
#pragma unroll
        for (int t = 0; t < 8; t++) {
            int c = WN1 + t * 8 + tig * 2;
            __half2 p0 = __floats2half2_rn(acc[m][t][0] + sBias[c], acc[m][t][1] + sBias[c + 1]);
            __half2 p1 = __floats2half2_rn(acc[m][t][2] + sBias[c], acc[m][t][3] + sBias[c + 1]);
            *(uint32_t*)(sA + lr0 * LDA + c) = *(uint32_t*)&p0;
            *(uint32_t*)(sA + lr1 * LDA + c) = *(uint32_t*)&p1;
        }
    }
    __syncthreads();

    float acc2[2][4][4];
#pragma unroll
    for (int m = 0; m < 2; m++)
#pragma unroll
        for (int t = 0; t < 4; t++)
#pragma unroll
            for (int j = 0; j < 4; j++) acc2[m][t][j] = 0.f;

#pragma unroll
    for (int ks = 0; ks < 8; ks++) {
        uint32_t a0[4], a1[4];
        ldsm4(a0, uA + (uint32_t)(a0off + ks * 16) * 2);
        ldsm4(a1, uA + (uint32_t)(a1off + ks * 16) * 2);
#pragma unroll
        for (int p = 0; p < 2; p++) {
            int boff = (WN2 + p * 16 + bsel) * LDA + ks * 16 + bhalf * 8;
            uint32_t b[4];
            ldsm4(b, uB2 + (uint32_t)boff * 2);
            mma16816(acc2[0][2 * p],     a0, b);
            mma16816(acc2[0][2 * p + 1], a0, b + 2);
            mma16816(acc2[1][2 * p],     a1, b);
            mma16816(acc2[1][2 * p + 1], a1, b + 2);
        }
    }

#pragma unroll
    for (int m = 0; m < 2; m++) {
        int r0 = row0 + WM + m * 16 + gid;
        int r1 = r0 + 8;
#pragma unroll
        for (int t = 0; t < 4; t++) {
            int c = WN2 + t * 8 + tig * 2;
            int head = (WN2 >> 3) + t;
            float sl  = acc2[m][t][0] * sAS[c] + acc2[m][t][1] * sAS[c + 1];
            float shh = acc2[m][t][2] * sAS[c] + acc2[m][t][3] * sAS[c + 1];
            float dl  = acc2[m][t][0] * sAD[c] + acc2[m][t][1] * sAD[c + 1];
            float dhh = acc2[m][t][2] * sAD[c] + acc2[m][t][3] * sAD[c + 1];
#pragma unroll
            for (int o = 1; o < 4; o <<= 1) {
                sl  += __shfl_xor_sync(FULLM, sl, o);
                shh += __shfl_xor_sync(FULLM, shh, o);
                dl  += __shfl_xor_sync(FULLM, dl, o);
                dhh += __shfl_xor_sync(FULLM, dhh, o);
            }
            if (tig == 0) {
                if (r0 < M) { asrc[(size_t)r0 * 8 + head] = sl;  adst[(size_t)r0 * 8 + head] = dl; }
                if (r1 < M) { asrc[(size_t)r1 * 8 + head] = shh; adst[(size_t)r1 * 8 + head] = dhh; }
            }
            __half2 p0 = __floats2half2_rn(acc2[m][t][0], acc2[m][t][1]);
            __half2 p1 = __floats2half2_rn(acc2[m][t][2], acc2[m][t][3]);
            if (r0 < M) *(uint32_t*)(outh1 + (size_t)r0 * 64 + c) = *(uint32_t*)&p0;
            if (r1 < M) *(uint32_t*)(outh1 + (size_t)r1 * 64 + c) = *(uint32_t*)&p1;
        }
    }
}
#define SMEM_G12 ((128 + 128 + 64) * 136 * 2 + 128 * 4 + 64 * 8 + 256)

// ------------------- GEMM3: out = aggh @ W2 + b2 ------------------------------
__global__ void __launch_bounds__(256) gemm3_kernel(
    const __half* __restrict__ Ag,
    const float* __restrict__ bias,
    float* __restrict__ out,
    int M)
{
    constexpr int K = 64, NC = 128, LDA = 72;
    const int tid = threadIdx.x;
    const int warp = tid >> 5;
    const int lane = tid & 31;
    const int gid = lane >> 2;
    const int tig = lane & 3;
    const int row0 = blockIdx.x * 128;
    const int WM = (warp & 3) * 32;
    const int WN = (warp >> 2) * 64;

    extern __shared__ char sm[];
    __half* sA = (__half*)sm;
    __half* sB = sA + 128 * LDA;
    float* sBias = (float*)(sB + NC * LDA);

    for (int idx = tid; idx < 128 * (K / 8); idx += 256) {
        int r = idx / (K / 8);
        int c = (idx % (K / 8)) * 8;
        int gr = row0 + r;
        uint4 v = make_uint4(0, 0, 0, 0);
        if (gr < M) v = *(const uint4*)(Ag + (size_t)gr * K + c);
        *(uint4*)(sA + r * LDA + c) = v;
    }
    for (int idx = tid; idx < NC * (K / 8); idx += 256) {
        int n = idx / (K / 8);
        int c = (idx % (K / 8)) * 8;
        *(uint4*)(sB + n * LDA + c) = *(const uint4*)(g_B3 + n * K + c);
    }
    if (tid < NC) sBias[tid] = bias[tid];
    __syncthreads();

    float acc[2][8][4];
#pragma unroll
    for (int m = 0; m < 2; m++)
#pragma unroll
        for (int t = 0; t < 8; t++)
#pragma unroll
            for (int j = 0; j < 4; j++) acc[m][t][j] = 0.f;

    const uint32_t uA = smem_u32(sA), uB = smem_u32(sB);
    const int a0off = (WM + (lane & 15)) * LDA + (lane >> 4) * 8;
    const int a1off = a0off + 16 * LDA;
    const int brow = lane & 7;
    const int bhalf = (lane >> 3) & 1;
    const int bsel = (lane >> 4) * 8 + brow;

#pragma unroll
    for (int ks = 0; ks < K / 16; ks++) {
        uint32_t a0[4], a1[4];
        ldsm4(a0, uA + (uint32_t)(a0off + ks * 16) * 2);
        ldsm4(a1, uA + (uint32_t)(a1off + ks * 16) * 2);
#pragma unroll
        for (int p = 0; p < 4; p++) {
            int boff = (WN + p * 16 + bsel) * LDA + ks * 16 + bhalf * 8;
            uint32_t b[4];
            ldsm4(b, uB + (uint32_t)boff * 2);
            mma16816(acc[0][2 * p],     a0, b);
            mma16816(acc[0][2 * p + 1], a0, b + 2);
            mma16816(acc[1][2 * p],     a1, b);
            mma16816(acc[1][2 * p + 1], a1, b + 2);
        }
    }

#pragma unroll
    for (int m = 0; m < 2; m++) {
        int r0 = row0 + WM + m * 16 + gid;
        int r1 = r0 + 8;
#pragma unroll
        for (int t = 0; t < 8; t++) {
            int c = WN + t * 8 + tig * 2;
            float b0 = sBias[c], b1v = sBias[c + 1];
            if (r0 < M) {
                float2 v = make_float2(acc[m][t][0] + b0, acc[m][t][1] + b1v);
                *(float2*)(out + (size_t)r0 * NC + c) = v;
            }
            if (r1 < M) {
                float2 v = make_float2(acc[m][t][2] + b0, acc[m][t][3] + b1v);
                *(float2*)(out + (size_t)r1 * NC + c) = v;
            }
        }
    }
}
#define SMEM_G3 ((128 + 128) * 72 * 2 + 128 * 4 + 256)

// ------------------- static init ---------------------------------------------
struct HxInit {
    cudaStream_t s2;
    cudaEvent_t evF, evJ;
    HxInit() {
        cudaStreamCreateWithFlags(&s2, cudaStreamNonBlocking);
        cudaEventCreateWithFlags(&evF, cudaEventDisableTiming);
        cudaEventCreateWithFlags(&evJ, cudaEventDisableTiming);
        cudaFuncSetAttribute(gemm12_kernel, cudaFuncAttributeMaxDynamicSharedMemorySize, SMEM_G12);
        cudaFuncSetAttribute(gemm3_kernel,  cudaFuncAttributeMaxDynamicSharedMemorySize, SMEM_G3);
    }
};
static HxInit g_hx;

// ------------------- CSR build (proven 3-kernel scan + rank scatter) ---------
__global__ void init_kernel()
{
    int i = blockIdx.x * 256 + threadIdx.x;
    if (i < NN) g_counts[i] = 1;   // slot 0 reserved for self loop
}

__global__ void count_kernel(const int* __restrict__ dst)
{
    int e = blockIdx.x * 256 + threadIdx.x;
    if (e < EE) g_erank[e] = atomicAdd(&g_counts[dst[e]], 1);
}

__global__ void __launch_bounds__(1024) scan1_kernel()
{
    __shared__ int wsum[32];
    int tid = threadIdx.x, lane = tid & 31, wid = tid >> 5;
    int idx = blockIdx.x * 1024 + tid;
    int v = (idx < NN) ? g_counts[idx] : 0;
    int x = v;
#pragma unroll
    for (int off = 1; off < 32; off <<= 1) {
        int y = __shfl_up_sync(FULLM, x, off);
        if (lane >= off) x += y;
    }
    if (lane == 31) wsum[wid] = x;
    __syncthreads();
    if (wid == 0) {
        int wv = wsum[lane];
#pragma unroll
        for (int off = 1; off < 32; off <<= 1) {
            int y = __shfl_up_sync(FULLM, wv, off);
            if (lane >= off) wv += y;
        }
        wsum[lane] = wv;
    }
    __syncthreads();
    int pre = (wid > 0) ? wsum[wid - 1] : 0;
    if (idx < NN) g_rowoff[idx] = x + pre - v;
    if (tid == 1023) g_blocksum[blockIdx.x] = x + pre;
}

__global__ void __launch_bounds__(64) scan2_kernel(int nblocks)
{
    __shared__ int s0tot;
    int tid = threadIdx.x, lane = tid & 31, wid = tid >> 5;
    int v = (tid < nblocks) ? g_blocksum[tid] : 0;
    int x = v;
#pragma unroll
    for (int off = 1; off < 32; off <<= 1) {
        int y = __shfl_up_sync(FULLM, x, off);
        if (lane >= off) x += y;
    }
    if (wid == 0 && lane == 31) s0tot = x;
    __syncthreads();
    int pre = (wid == 1) ? s0tot : 0;
    int excl = x - v + pre;
    if (tid < nblocks) g_blocksum[tid] = excl;
    if (tid == nblocks - 1) g_rowoff[NN] = excl + v;
}

// adds block offsets + writes self-loop entry at slot 0 of each row
__global__ void __launch_bounds__(1024) scan3_kernel()
{
    int idx = blockIdx.x * 1024 + threadIdx.x;
    if (idx < NN) {
        int off = g_rowoff[idx] + g_blocksum[blockIdx.x];
        g_rowoff[idx] = off;
        g_csrsrc[off] = idx;    // self loop
    }
}

// pure load/store scatter (no atomics)
__global__ void scatter_kernel(const int* __restrict__ src, const int* __restrict__ dst)
{
    int e = blockIdx.x * 256 + threadIdx.x;
    if (e < EE) {
        int d = dst[e];
        g_csrsrc[g_rowoff[d] + g_erank[e]] = src[e];
    }
}

// ------------------- GAT conv1 aggregation (lane-parallel weights) -----------
__global__ void __launch_bounds__(256) agg1_kernel(const float* __restrict__ b1)
{
    int w = (blockIdx.x * blockDim.x + threadIdx.x) >> 5;
    int lane = threadIdx.x & 31;
    if (w >= NN) return;
    int head = lane >> 2;
    int c0 = lane * 2;
    int beg = g_rowoff[w], end = g_rowoff[w + 1];

    float ad8 = g_adst1[w * 8 + (lane & 7)];   // lane h (mod 8) holds head h's adst
    float adh = __shfl_sync(FULLM, ad8, head);

    float a0 = 0.f, a1 = 0.f, sSum = 0.f;
    float b0a = 0.f, b1a = 0.f;
    float c0a = 0.f, c1a = 0.f;
    float d0a = 0.f, d1a = 0.f;

    for (int base = beg; base < end; base += 32) {
        int n = end - base;
        int kmax = n < 32 ? n : 32;
        int sl = (lane < kmax) ? g_csrsrc[base + lane] : 0;
        int k = 0;
        for (; k + 4 <= kmax; k += 4) {
            // 32 lanes cover 4 edges x 8 heads: edge = k + (lane>>3), head = lane&7
            int sj = __shfl_sync(FULLM, sl, k + (lane >> 3));
            float e4 = __expf(leaky(g_asrc1[sj * 8 + (lane & 7)] + ad8));
            int s0 = __shfl_sync(FULLM, sl, k);
            int s1 = __shfl_sync(FULLM, sl, k + 1);
            int s2 = __shfl_sync(FULLM, sl, k + 2);
            int s3 = __shfl_sync(FULLM, sl, k + 3);
            float e0 = __shfl_sync(FULLM, e4, head);
            float e1 = __shfl_sync(FULLM, e4, 8 + head);
            float e2 = __shfl_sync(FULLM, e4, 16 + head);
            float e3 = __shfl_sync(FULLM, e4, 24 + head);
            float2 h0 = __half22float2(*(const __half2*)(g_h1h + s0 * 64 + c0));
            float2 h1 = __half22float2(*(const __half2*)(g_h1h + s1 * 64 + c0));
            float2 h2 = __half22float2(*(const __half2*)(g_h1h + s2 * 64 + c0));
            float2 h3 = __half22float2(*(const __half2*)(g_h1h + s3 * 64 + c0));
            a0 = fmaf(e0, h0.x, a0);  a1 = fmaf(e0, h0.y, a1);
            b0a = fmaf(e1, h1.x, b0a); b1a = fmaf(e1, h1.y, b1a);
            c0a = fmaf(e2, h2.x, c0a); c1a = fmaf(e2, h2.y, c1a);
            d0a = fmaf(e3, h3.x, d0a); d1a = fmaf(e3, h3.y, d1a);
            sSum += e0 + e1 + e2 + e3;
        }
        for (; k < kmax; k++) {
            int s = __shfl_sync(FULLM, sl, k);
            float e = __expf(leaky(g_asrc1[s * 8 + head] + adh));
            float2 hv = __half22float2(*(const __half2*)(g_h1h + s * 64 + c0));
            a0 = fmaf(e, hv.x, a0); a1 = fmaf(e, hv.y, a1);
            sSum += e;
        }
    }
    a0 += b0a + c0a + d0a;
    a1 += b1a + c1a + d1a;
    float inv = 1.f / sSum;
    float o0 = a0 * inv + b1[c0];
    float o1 = a1 * inv + b1[c0 + 1];
    o0 = o0 > 0.f ? o0 : expm1f(o0);
    o1 = o1 > 0.f ? o1 : expm1f(o1);
    __half2 p = __floats2half2_rn(o0, o1);
    *(uint32_t*)(g_hm + w * 64 + c0) = *(uint32_t*)&p;

    float ps = o0 * g_wsd[c0] + o1 * g_wsd[c0 + 1];
    float pd = o0 * g_wsd[64 + c0] + o1 * g_wsd[64 + c0 + 1];
#pragma unroll
    for (int off = 16; off; off >>= 1) {
        ps += __shfl_xor_sync(FULLM, ps, off);
        pd += __shfl_xor_sync(FULLM, pd, off);
    }
    if (lane == 0) { g_asrc2[w] = ps; g_adst2[w] = pd; }
}

// ------------------- GAT conv2 aggregation -----------------------------------
__global__ void __launch_bounds__(256) agg2_kernel()
{
    int w = (blockIdx.x * blockDim.x + threadIdx.x) >> 5;
    int lane = threadIdx.x & 31;
    if (w >= NN) return;
    int c0 = lane * 2;
    int beg = g_rowoff[w], end = g_rowoff[w + 1];
    float adh = g_adst2[w];

    float a0 = 0.f, a1 = 0.f, sSum = 0.f;
    float b0a = 0.f, b1a = 0.f;
    float c0a = 0.f, c1a = 0.f;
    float d0a = 0.f, d1a = 0.f;

    for (int base = beg; base < end; base += 32) {
        int n = end - base;
        int kmax = n < 32 ? n : 32;
        int sl = 0;
        float el = 0.f;
        if (lane < kmax) {
            sl = g_csrsrc[base + lane];
            el = __expf(leaky(g_asrc2[sl] + adh));
        }
        sSum += el;
        int k = 0;
        for (; k + 4 <= kmax; k += 4) {
            int s0 = __shfl_sync(FULLM, sl, k);
            int s1 = __shfl_sync(FULLM, sl, k + 1);
            int s2 = __shfl_sync(FULLM, sl, k + 2);
            int s3 = __shfl_sync(FULLM, sl, k + 3);
            float e0 = __shfl_sync(FULLM, el, k);
            float e1 = __shfl_sync(FULLM, el, k + 1);
            float e2 = __shfl_sync(FULLM, el, k + 2);
            float e3 = __shfl_sync(FULLM, el, k + 3);
            float2 h0 = __half22float2(*(const __half2*)(g_hm + s0 * 64 + c0));
            float2 h1 = __half22float2(*(const __half2*)(g_hm + s1 * 64 + c0));
            float2 h2 = __half22float2(*(const __half2*)(g_hm + s2 * 64 + c0));
            float2 h3 = __half22float2(*(const __half2*)(g_hm + s3 * 64 + c0));
            a0 = fmaf(e0, h0.x, a0);  a1 = fmaf(e0, h0.y, a1);
            b0a = fmaf(e1, h1.x, b0a); b1a = fmaf(e1, h1.y, b1a);
            c0a = fmaf(e2, h2.x, c0a); c1a = fmaf(e2, h2.y, c1a);
            d0a = fmaf(e3, h3.x, d0a); d1a = fmaf(e3, h3.y, d1a);
        }
        for (; k < kmax; k++) {
            int s = __shfl_sync(FULLM, sl, k);
            float e = __shfl_sync(FULLM, el, k);
            float2 hv = __half22float2(*(const __half2*)(g_hm + s * 64 + c0));
            a0 = fmaf(e, hv.x, a0); a1 = fmaf(e, hv.y, a1);
        }
    }
    a0 += b0a + c0a + d0a;
    a1 += b1a + c1a + d1a;
#pragma unroll
    for (int off = 16; off; off >>= 1)
        sSum += __shfl_xor_sync(FULLM, sSum, off);
    float inv = 1.f / sSum;
    __half2 p = __floats2half2_rn(a0 * inv, a1 * inv);
    *(uint32_t*)(g_aggh + w * 64 + c0) = *(uint32_t*)&p;
}

// ------------------- launch --------------------------------------------------
extern "C" void kernel_launch(void* const* d_in, const int* in_sizes, int n_in,
                              void* d_out, int out_size)
{
    (void)in_sizes; (void)n_in; (void)out_size;
    const float* x        = (const float*)d_in[0];
    const int*   ei       = (const int*)d_in[1];
    const float* W_map    = (const float*)d_in[2];
    const float* b_map    = (const float*)d_in[3];
    const float* W1       = (const float*)d_in[4];
    const float* att_src1 = (const float*)d_in[5];
    const float* att_dst1 = (const float*)d_in[6];
    const float* b1       = (const float*)d_in[7];
    const float* W2       = (const float*)d_in[8];
    const float* att_src2 = (const float*)d_in[9];
    const float* att_dst2 = (const float*)d_in[10];
    const float* b2       = (const float*)d_in[11];
    float* out = (float*)d_out;
    const int* src = ei;
    const int* dst = ei + EE;

    __half *p_h1h, *p_aggh;
    float *p_as1, *p_ad1;
    cudaGetSymbolAddress((void**)&p_h1h, g_h1h);
    cudaGetSymbolAddress((void**)&p_aggh, g_aggh);
    cudaGetSymbolAddress((void**)&p_as1, g_asrc1);
    cudaGetSymbolAddress((void**)&p_ad1, g_adst1);

    const int GEMM_BLOCKS = (NN + 127) / 128;
    const int N_BLOCKS    = (NN + 255) / 256;
    const int E_BLOCKS    = (EE + 255) / 256;
    const int WARP_BLOCKS = NN / 8;
    const int SCAN_BLOCKS = (NN + 1023) / 1024;

    cudaStream_t s2 = g_hx.s2;

    prep_w_kernel<<<129, 256>>>(W_map, W1, W2, att_src2, att_dst2);

    cudaEventRecord(g_hx.evF, 0);
    cudaStreamWaitEvent(s2, g_hx.evF, 0);
    init_kernel<<<N_BLOCKS, 256, 0, s2>>>();
    count_kernel<<<E_BLOCKS, 256, 0, s2>>>(dst);

    gemm12_kernel<<<GEMM_BLOCKS, 256, SMEM_G12>>>(
        x, b_map, att_src1, att_dst1, p_h1h, p_as1, p_ad1, NN);

    scan1_kernel<<<SCAN_BLOCKS, 1024, 0, s2>>>();
    scan2_kernel<<<1, 64, 0, s2>>>(SCAN_BLOCKS);
    scan3_kernel<<<SCAN_BLOCKS, 1024, 0, s2>>>();
    scatter_kernel<<<E_BLOCKS, 256, 0, s2>>>(src, dst);
    cudaEventRecord(g_hx.evJ, s2);

    cudaStreamWaitEvent(0, g_hx.evJ, 0);

    agg1_kernel<<<WARP_BLOCKS, 256>>>(b1);
    agg2_kernel<<<WARP_BLOCKS, 256>>>();
    gemm3_kernel<<<GEMM_BLOCKS, 256, SMEM_G3>>>(p_aggh, b2, out, NN);
}